// round 9
// baseline (speedup 1.0000x reference)
#include <cuda_runtime.h>
#include <math.h>

// Shapes (fixed for this problem)
#define NB 16
#define CI 64
#define CO 64
#define HH 256
#define WW 256
#define M0 32
#define M1 32

// Scratch (device globals; no allocation allowed in kernel_launch)
__device__ __align__(256) float g_Xw [(size_t)NB*CI*HH*M1*2]; // 67 MB  [b][i][h][l]{re,im}
__device__ __align__(256) float g_Xm [(size_t)NB*CI*M0*M1*2]; // 8.4 MB [b][i][k*32+l]{re,im}
__device__ __align__(256) float g_Yb [(size_t)NB*CO*M0*M1*2]; // 8.4 MB [b][o][k*32+l]{re,im}
__device__ __align__(256) float g_Z  [(size_t)NB*CO*HH*M1*2]; // 67 MB  [b][o][h][l]{re,im}
__device__ __align__(256) float2 g_Wt[(size_t)M0*M1*CI*CO];   // 33.5MB [kl][i*64+o]{re,im}
__device__ __align__(256) float g_Tfwd[WW*M1*2];              // forward DFT-w matrix [w][2l|2l+1]
__device__ __align__(256) float g_Tinv[M1*2*WW];              // inverse DFT-w matrix [2l|2l+1][w]
__device__ __align__(256) float g_gamma[NB*CO];
__device__ __align__(256) float g_beta [NB*CO];

__device__ __forceinline__ float gelu_tanh(float x) {
    float u = 0.7978845608028654f * (x + 0.044715f * x * x * x);
    float t;
    asm("tanh.approx.f32 %0, %1;" : "=f"(t) : "f"(u));
    return 0.5f * x * (1.0f + t);
}

// ---------------------------------------------------------------------------
// setupK (grid 4096, 256 thr):
//  * every block: transpose one 32x32 tile of (w_real,w_imag) into
//    g_Wt[kl][p] (p = i*64+o), coalesced both sides via smem tile.
//  * blocks 0..31: build DFT twiddle tables (exact integer phase mod 256).
//  * block 4095:  FiLM MLP -> g_gamma/g_beta.
// ---------------------------------------------------------------------------
__global__ __launch_bounds__(256) void setupK(const float* __restrict__ wr,
                                              const float* __restrict__ wi,
                                              const float* __restrict__ t_emb,
                                              const float* __restrict__ w1,
                                              const float* __restrict__ b1,
                                              const float* __restrict__ w2,
                                              const float* __restrict__ b2) {
    __shared__ float tr[32][33];
    __shared__ float ti[32][33];
    int tid = threadIdx.x;
    int p0  = (blockIdx.x >> 5) << 5;     // 128 p-tiles
    int kl0 = (blockIdx.x & 31) << 5;     // 32 kl-tiles
    {
        int c = tid & 31;
#pragma unroll
        for (int pass = 0; pass < 4; pass++) {
            int r = (tid >> 5) + (pass << 3);
            tr[r][c] = wr[(size_t)(p0 + r) * 1024 + kl0 + c];
            ti[r][c] = wi[(size_t)(p0 + r) * 1024 + kl0 + c];
        }
        __syncthreads();
#pragma unroll
        for (int pass = 0; pass < 4; pass++) {
            int r = (tid >> 5) + (pass << 3);
            g_Wt[(size_t)(kl0 + r) * 4096 + p0 + c] = make_float2(tr[c][r], ti[c][r]);
        }
    }

    if (blockIdx.x < 32) {
        int p = blockIdx.x * 256 + tid;   // 0..8191
        const float TWO_PI = 6.283185307179586f;
        {   // Forward table
            int w = p >> 5, l = p & 31;
            int m = (w * l) & 255;
            float s, c; sincosf(TWO_PI * (float)m * (1.0f/256.0f), &s, &c);
            g_Tfwd[w*64 + 2*l    ] =  c;
            g_Tfwd[w*64 + 2*l + 1] = -s;
        }
        {   // Inverse table, full ortho norm folded
            const float norm = 1.0f / 65536.0f;
            int l = p >> 8, w = p & 255;
            int m = (l * w) & 255;
            float s, c; sincosf(TWO_PI * (float)m * (1.0f/256.0f), &s, &c);
            g_Tinv[(2*l  )*WW + w] = norm * (l ? 2.0f : 1.0f) * c;
            g_Tinv[(2*l+1)*WW + w] = l ? (-2.0f * norm * s) : 0.0f;
        }
    }

    if (blockIdx.x == 4095) {             // FiLM
        __shared__ float tsh[NB*CI];
        __shared__ float hsh[NB*CI];
        __syncthreads();
        for (int p = tid; p < NB*CI; p += 256) tsh[p] = t_emb[p];
        __syncthreads();
        for (int p = tid; p < NB*CI; p += 256) {
            int b = p >> 6, j = p & 63;
            float s = b1[j];
            for (int i = 0; i < CI; i++) s += tsh[(b<<6)+i] * w1[i*CI + j];
            hsh[p] = s / (1.0f + expf(-s));
        }
        __syncthreads();
        for (int p = tid; p < NB*2*CO; p += 256) {
            int b = p >> 7, j = p & 127;
            float s = b2[j];
            for (int i = 0; i < CI; i++) s += hsh[(b<<6)+i] * w2[i*(2*CO) + j];
            if (j < CO) g_gamma[(b<<6)+j] = s;
            else        g_beta [(b<<6)+j-CO] = s;
        }
    }
}

// ---------------------------------------------------------------------------
// Stage A with real-input symmetry (halved FMA). One block per (b,h).
// ---------------------------------------------------------------------------
#define A3_U   0
#define A3_V   8448      // 64*132
#define A3_TC  16896
#define A3_TS  21282     // 16896 + 129*34
#define A3_SMEM (21282 + 128*34)   // 25634 floats

__global__ __launch_bounds__(256) void stageA3(const float* __restrict__ x) {
    extern __shared__ float sm[];
    float* U  = sm + A3_U;
    float* V  = sm + A3_V;
    float* Tc = sm + A3_TC;
    float* Ts = sm + A3_TS;
    int tid = threadIdx.x, lane = tid & 31, wid = tid >> 5;
    int b = blockIdx.x >> 8;
    int h = blockIdx.x & 255;

    for (int p = tid; p < 129*32; p += 256) {
        int w = p >> 5, l = p & 31;
        float2 cs = *(const float2*)&g_Tfwd[w*64 + 2*l];
        Tc[w*34 + l] = cs.x;
        if (w < 128) Ts[w*34 + l] = cs.y;
    }

    size_t xbase = (size_t)b * CI * HH * WW + (size_t)h * WW;
    for (int i = wid; i < 64; i += 8) {
        const float4* xr = (const float4*)(x + xbase + (size_t)i * HH * WW);
        float4 A4 = xr[lane];
        float4 B4 = xr[63 - lane];
        float m0 = __shfl_up_sync(0xffffffffu, B4.x, 1);
        float4 u, v;
        if (lane == 0) { u.x = A4.x;      v.x = 0.0f; }
        else           { u.x = A4.x + m0; v.x = A4.x - m0; }
        u.y = A4.y + B4.w;  v.y = A4.y - B4.w;
        u.z = A4.z + B4.z;  v.z = A4.z - B4.z;
        u.w = A4.w + B4.y;  v.w = A4.w - B4.y;
        *(float4*)&U[i*132 + 4*lane] = u;
        *(float4*)&V[i*132 + 4*lane] = v;
        if (lane == 31) U[i*132 + 128] = B4.x;
    }
    __syncthreads();

    int i0 = (tid >> 4) << 2;
    int l0 = (tid & 15) << 1;
    float re[4][2], im[4][2];
#pragma unroll
    for (int r = 0; r < 4; r++) { re[r][0]=re[r][1]=im[r][0]=im[r][1]=0.0f; }

    const float* U0  = U + i0*132;
    const float* V0  = V + i0*132;
    const float* Tcp = Tc + l0;
    const float* Tsp = Ts + l0;
#pragma unroll 3
    for (int w = 0; w < 129; w++) {
        float2 c = *(const float2*)&Tcp[w*34];
        float u0 = U0[w], u1 = U0[132+w], u2 = U0[264+w], u3 = U0[396+w];
        re[0][0] += u0*c.x; re[0][1] += u0*c.y;
        re[1][0] += u1*c.x; re[1][1] += u1*c.y;
        re[2][0] += u2*c.x; re[2][1] += u2*c.y;
        re[3][0] += u3*c.x; re[3][1] += u3*c.y;
    }
#pragma unroll 4
    for (int w = 0; w < 128; w++) {
        float2 s = *(const float2*)&Tsp[w*34];
        float v0 = V0[w], v1 = V0[132+w], v2 = V0[264+w], v3 = V0[396+w];
        im[0][0] += v0*s.x; im[0][1] += v0*s.y;
        im[1][0] += v1*s.x; im[1][1] += v1*s.y;
        im[2][0] += v2*s.x; im[2][1] += v2*s.y;
        im[3][0] += v3*s.x; im[3][1] += v3*s.y;
    }
#pragma unroll
    for (int r = 0; r < 4; r++) {
        size_t idx = (((size_t)(b*64 + i0 + r) * 256 + h) * 64) + 2*l0;
        *(float4*)&g_Xw[idx] = make_float4(re[r][0], im[r][0], re[r][1], im[r][1]);
    }
}

// ---------------------------------------------------------------------------
// Stage B: Xm[b,i,k,l] = sum_h Xw[b,i,h,l] * e^{-2*pi*i*k*h/256}
// ---------------------------------------------------------------------------
__global__ __launch_bounds__(256) void stageB() {
    __shared__ float2 tw[256];
    int tid = threadIdx.x;
    { float s, c; sincosf(6.283185307179586f * (float)tid * (1.0f/256.0f), &s, &c);
      tw[tid] = make_float2(c, s); }
    __syncthreads();
    int blk = blockIdx.x;                             // b*64+i
    const float2* Xp = (const float2*)(g_Xw) + (size_t)blk * HH * M1;
    int l  = tid & 31;
    int k0 = tid >> 5;
    float2 acc[4];
    int mt[4];
#pragma unroll
    for (int t = 0; t < 4; t++) { acc[t] = make_float2(0.f, 0.f); mt[t] = 0; }
    for (int h = 0; h < HH; h++) {
        float2 xv = Xp[h*M1 + l];
#pragma unroll
        for (int t = 0; t < 4; t++) {
            float2 e = tw[mt[t]];
            acc[t].x += xv.x*e.x + xv.y*e.y;          // (xr+ixi)*(c - i s)
            acc[t].y += xv.y*e.x - xv.x*e.y;
            mt[t] = (mt[t] + k0 + (t << 3)) & 255;
        }
    }
    float2* Om = (float2*)g_Xm + (size_t)blk * (M0*M1);
#pragma unroll
    for (int t = 0; t < 4; t++) {
        int k = k0 + (t << 3);
        Om[k*M1 + l] = acc[t];
    }
}

// ---------------------------------------------------------------------------
// Mode mix + gamma fold. W read COALESCED from pre-transposed g_Wt[kl][p].
// Y[b,o,kl] = (1+gamma[b,o]) * sum_i Xm[b,i,kl] * W[i,o,kl]
// ---------------------------------------------------------------------------
__global__ __launch_bounds__(256) void mixK() {
    __shared__ float2 Wsh[CI*CO];    // 32 KB
    __shared__ float2 Xsh[NB*CI];    //  8 KB
    int kl = blockIdx.x;
    int tid = threadIdx.x;
    const float4* wsrc = (const float4*)(g_Wt + (size_t)kl * 4096);
    for (int q = tid; q < 2048; q += 256)
        ((float4*)Wsh)[q] = wsrc[q];                  // coalesced 16B
    for (int p = tid; p < NB*CI; p += 256)
        Xsh[p] = ((const float2*)g_Xm)[(size_t)p*1024 + kl];
    __syncthreads();
#pragma unroll
    for (int q = 0; q < 4; q++) {
        int idx = tid + q*256;                        // b*64+o
        int b = idx >> 6, o = idx & 63;
        float yr = 0.f, yi = 0.f;
#pragma unroll 8
        for (int i = 0; i < CI; i++) {
            float2 xv = Xsh[(b << 6) + i];
            float2 wv = Wsh[(i << 6) + o];
            yr += xv.x*wv.x - xv.y*wv.y;
            yi += xv.x*wv.y + xv.y*wv.x;
        }
        float g = 1.0f + g_gamma[idx];
        ((float2*)g_Yb)[(size_t)idx*1024 + kl] = make_float2(g*yr, g*yi);
    }
}

// ---------------------------------------------------------------------------
// Stage C: Z[b,o,h,l] = sum_{k<32} Y[b,o,k,l] * e^{+2*pi*i*k*h/256}
// ---------------------------------------------------------------------------
__global__ __launch_bounds__(256) void stageC() {
    __shared__ float2 tw[256];
    int tid = threadIdx.x;
    { float s, c; sincosf(6.283185307179586f * (float)tid * (1.0f/256.0f), &s, &c);
      tw[tid] = make_float2(c, s); }
    __syncthreads();
    int blk = blockIdx.x;                             // b*64+o
    const float2* Yp = (const float2*)g_Yb + (size_t)blk * (M0*M1);
    int l  = tid & 31;
    int h0 = tid >> 5;
    float2 acc[32];
#pragma unroll
    for (int t = 0; t < 32; t++) acc[t] = make_float2(0.f, 0.f);
    for (int k = 0; k < M0; k++) {
        float2 yv = Yp[k*M1 + l];
        int mm = (k * h0) & 255;
        int st = (k << 3) & 255;
#pragma unroll
        for (int t = 0; t < 32; t++) {
            float2 e = tw[mm];
            acc[t].x += yv.x*e.x - yv.y*e.y;
            acc[t].y += yv.x*e.y + yv.y*e.x;
            mm = (mm + st) & 255;
        }
    }
    float2* Zp = (float2*)g_Z + (size_t)blk * HH * M1;
#pragma unroll
    for (int t = 0; t < 32; t++)
        Zp[(h0 + (t << 3))*M1 + l] = acc[t];
}

// ---------------------------------------------------------------------------
// Fused inverse-w DFT + FiLM beta + bypass 1x1 conv + GELU.
// Spectral loop FIRST (pure smem FFMA) with 8-deep x prefetch issued before
// it, so bypass DRAM latency hides under 4096 FFMAs.
// ---------------------------------------------------------------------------
#define ZPAD 68
__global__ __launch_bounds__(256) void specfinalK(const float* __restrict__ x,
                                                  const float* __restrict__ bw,
                                                  const float* __restrict__ bb,
                                                  float* __restrict__ out) {
    extern __shared__ float sm[];
    float* tinv_s = sm;                       // [64][256]  16384
    float* zzs    = sm + 16384;               // [64][ZPAD]  4352
    float* bwsh   = zzs + 64*ZPAD;            // [64][64]    4096
    float* beta_s = bwsh + 4096;              // [64]
    int tid = threadIdx.x;
    int b = blockIdx.x >> 8;
    int h = blockIdx.x & 255;

    for (int p = tid; p < 4096; p += 256)
        *(float4*)&tinv_s[p << 2] = *(const float4*)&g_Tinv[p << 2];
    for (int p = tid; p < 1024; p += 256)
        *(float4*)&bwsh[p << 2] = *(const float4*)&bw[p << 2];
    for (int p = tid; p < 2048; p += 256) {
        int o = p >> 5, l = p & 31;
        float2 v = ((const float2*)g_Z)[((size_t)(b*64 + o) * 256 + h) * 32 + l];
        zzs[(2*l  )*ZPAD + o] = v.x;
        zzs[(2*l+1)*ZPAD + o] = v.y;
    }
    if (tid < 64) beta_s[tid] = g_beta[b*64 + tid] + bb[tid];
    __syncthreads();

    float acc[64];
#pragma unroll
    for (int o = 0; o < 64; o++) acc[o] = 0.0f;

    // Kick off first bypass channel loads NOW; they complete under spectral.
    size_t xb = (size_t)b * CI * HH * WW + (size_t)h * WW + tid;
    float creg[8];
#pragma unroll
    for (int j = 0; j < 8; j++) creg[j] = x[xb + (size_t)j * HH * WW];

    // Spectral part: acc[o] += ZZ[l'][o] * Tinv[l'][w]
    const float* tp = tinv_s + tid;
#pragma unroll 2
    for (int lp = 0; lp < 64; lp++) {
        float tv = tp[lp << 8];
        const float* zr = zzs + lp * ZPAD;
#pragma unroll
        for (int og = 0; og < 16; og++) {
            float4 z = *(const float4*)&zr[og << 2];
            acc[4*og+0] += z.x * tv;
            acc[4*og+1] += z.y * tv;
            acc[4*og+2] += z.z * tv;
            acc[4*og+3] += z.w * tv;
        }
    }

    // Bypass part: acc[o] += sum_i bw[o][i] * x[b,i,h,w], 8-channel pipeline
    for (int i = 0; i < CI; i += 8) {
        float nreg[8];
        if (i + 8 < CI) {
#pragma unroll
            for (int j = 0; j < 8; j++)
                nreg[j] = x[xb + (size_t)(i + 8 + j) * HH * WW];
        }
#pragma unroll
        for (int o = 0; o < 64; o++) {
            float4 wa = *(const float4*)&bwsh[(o << 6) + i];
            float4 wb = *(const float4*)&bwsh[(o << 6) + i + 4];
            acc[o] += wa.x*creg[0] + wa.y*creg[1] + wa.z*creg[2] + wa.w*creg[3]
                    + wb.x*creg[4] + wb.y*creg[5] + wb.z*creg[6] + wb.w*creg[7];
        }
#pragma unroll
        for (int j = 0; j < 8; j++) creg[j] = nreg[j];
    }

    size_t ob = (size_t)b * CO * HH * WW + (size_t)h * WW + tid;
#pragma unroll 8
    for (int o = 0; o < 64; o++)
        out[ob + (size_t)o * HH * WW] = gelu_tanh(acc[o] + beta_s[o]);
}

// ---------------------------------------------------------------------------
extern "C" void kernel_launch(void* const* d_in, const int* in_sizes, int n_in,
                              void* d_out, int out_size) {
    const float* x      = (const float*)d_in[0];
    const float* t_emb  = (const float*)d_in[1];
    const float* w_real = (const float*)d_in[2];
    const float* w_imag = (const float*)d_in[3];
    const float* fw1    = (const float*)d_in[4];
    const float* fb1    = (const float*)d_in[5];
    const float* fw2    = (const float*)d_in[6];
    const float* fb2    = (const float*)d_in[7];
    const float* bw     = (const float*)d_in[8];
    const float* bb     = (const float*)d_in[9];
    float* out = (float*)d_out;

    const int smemA = A3_SMEM * sizeof(float);                       // 102536
    const int smemF = (16384 + 64*ZPAD + 4096 + 64) * sizeof(float); // 99584
    cudaFuncSetAttribute(stageA3,    cudaFuncAttributeMaxDynamicSharedMemorySize, smemA);
    cudaFuncSetAttribute(specfinalK, cudaFuncAttributeMaxDynamicSharedMemorySize, smemF);

    setupK<<<4096, 256>>>(w_real, w_imag, t_emb, fw1, fb1, fw2, fb2); // 1
    stageA3<<<NB*HH, 256, smemA>>>(x);                                // 2
    stageB<<<NB*CI, 256>>>();                                         // 3
    mixK<<<M0*M1, 256>>>();                                           // 4 <- profiled
    stageC<<<NB*CO, 256>>>();                                         // 5
    specfinalK<<<NB*HH, 256, smemF>>>(x, bw, bb, out);                // 6
}

// round 10
// speedup vs baseline: 1.4207x; 1.4207x over previous
#include <cuda_runtime.h>
#include <math.h>

// Shapes (fixed for this problem)
#define NB 16
#define CI 64
#define CO 64
#define HH 256
#define WW 256
#define M0 32
#define M1 32

// Scratch (device globals; no allocation allowed in kernel_launch)
__device__ __align__(256) float g_Xw [(size_t)NB*CI*HH*M1*2]; // 67 MB  [b][i][h][l]{re,im}
__device__ __align__(256) float g_Xm [(size_t)NB*CI*M0*M1*2]; // 8.4 MB [b][i][k*32+l]{re,im}
__device__ __align__(256) float g_Yb [(size_t)NB*CO*M0*M1*2]; // 8.4 MB [b][o][k*32+l]{re,im}
__device__ __align__(256) float g_Z  [(size_t)NB*CO*HH*M1*2]; // 67 MB  [b][o][h][l]{re,im}
__device__ __align__(256) float2 g_Wt[(size_t)M0*M1*CI*CO];   // 33.5MB [kl][i*64+o]{re,im}
__device__ __align__(256) float g_Tfwd[WW*M1*2];              // forward DFT-w matrix [w][2l|2l+1]
__device__ __align__(256) float g_Tinv[M1*2*WW];              // inverse DFT-w matrix [2l|2l+1][w]
__device__ __align__(256) float g_gamma[NB*CO];
__device__ __align__(256) float g_beta [NB*CO];

__device__ __forceinline__ float gelu_tanh(float x) {
    float u = 0.7978845608028654f * (x + 0.044715f * x * x * x);
    float t;
    asm("tanh.approx.f32 %0, %1;" : "=f"(t) : "f"(u));
    return 0.5f * x * (1.0f + t);
}

// ---------------------------------------------------------------------------
// setupK (grid 4096, 256 thr): W transpose + DFT tables + FiLM.
// ---------------------------------------------------------------------------
__global__ __launch_bounds__(256) void setupK(const float* __restrict__ wr,
                                              const float* __restrict__ wi,
                                              const float* __restrict__ t_emb,
                                              const float* __restrict__ w1,
                                              const float* __restrict__ b1,
                                              const float* __restrict__ w2,
                                              const float* __restrict__ b2) {
    __shared__ float tr[32][33];
    __shared__ float ti[32][33];
    int tid = threadIdx.x;
    int p0  = (blockIdx.x >> 5) << 5;     // 128 p-tiles
    int kl0 = (blockIdx.x & 31) << 5;     // 32 kl-tiles
    {
        int c = tid & 31;
#pragma unroll
        for (int pass = 0; pass < 4; pass++) {
            int r = (tid >> 5) + (pass << 3);
            tr[r][c] = wr[(size_t)(p0 + r) * 1024 + kl0 + c];
            ti[r][c] = wi[(size_t)(p0 + r) * 1024 + kl0 + c];
        }
        __syncthreads();
#pragma unroll
        for (int pass = 0; pass < 4; pass++) {
            int r = (tid >> 5) + (pass << 3);
            g_Wt[(size_t)(kl0 + r) * 4096 + p0 + c] = make_float2(tr[c][r], ti[c][r]);
        }
    }

    if (blockIdx.x < 32) {
        int p = blockIdx.x * 256 + tid;   // 0..8191
        const float TWO_PI = 6.283185307179586f;
        {   // Forward table
            int w = p >> 5, l = p & 31;
            int m = (w * l) & 255;
            float s, c; sincosf(TWO_PI * (float)m * (1.0f/256.0f), &s, &c);
            g_Tfwd[w*64 + 2*l    ] =  c;
            g_Tfwd[w*64 + 2*l + 1] = -s;
        }
        {   // Inverse table, full ortho norm folded
            const float norm = 1.0f / 65536.0f;
            int l = p >> 8, w = p & 255;
            int m = (l * w) & 255;
            float s, c; sincosf(TWO_PI * (float)m * (1.0f/256.0f), &s, &c);
            g_Tinv[(2*l  )*WW + w] = norm * (l ? 2.0f : 1.0f) * c;
            g_Tinv[(2*l+1)*WW + w] = l ? (-2.0f * norm * s) : 0.0f;
        }
    }

    if (blockIdx.x == 4095) {             // FiLM
        __shared__ float tsh[NB*CI];
        __shared__ float hsh[NB*CI];
        __syncthreads();
        for (int p = tid; p < NB*CI; p += 256) tsh[p] = t_emb[p];
        __syncthreads();
        for (int p = tid; p < NB*CI; p += 256) {
            int b = p >> 6, j = p & 63;
            float s = b1[j];
            for (int i = 0; i < CI; i++) s += tsh[(b<<6)+i] * w1[i*CI + j];
            hsh[p] = s / (1.0f + expf(-s));
        }
        __syncthreads();
        for (int p = tid; p < NB*2*CO; p += 256) {
            int b = p >> 7, j = p & 127;
            float s = b2[j];
            for (int i = 0; i < CI; i++) s += hsh[(b<<6)+i] * w2[i*(2*CO) + j];
            if (j < CO) g_gamma[(b<<6)+j] = s;
            else        g_beta [(b<<6)+j-CO] = s;
        }
    }
}

// ---------------------------------------------------------------------------
// Stage A with real-input symmetry (halved FMA). One block per (b,h).
// ---------------------------------------------------------------------------
#define A3_U   0
#define A3_V   8448      // 64*132
#define A3_TC  16896
#define A3_TS  21282     // 16896 + 129*34
#define A3_SMEM (21282 + 128*34)   // 25634 floats

__global__ __launch_bounds__(256) void stageA3(const float* __restrict__ x) {
    extern __shared__ float sm[];
    float* U  = sm + A3_U;
    float* V  = sm + A3_V;
    float* Tc = sm + A3_TC;
    float* Ts = sm + A3_TS;
    int tid = threadIdx.x, lane = tid & 31, wid = tid >> 5;
    int b = blockIdx.x >> 8;
    int h = blockIdx.x & 255;

    for (int p = tid; p < 129*32; p += 256) {
        int w = p >> 5, l = p & 31;
        float2 cs = *(const float2*)&g_Tfwd[w*64 + 2*l];
        Tc[w*34 + l] = cs.x;
        if (w < 128) Ts[w*34 + l] = cs.y;
    }

    size_t xbase = (size_t)b * CI * HH * WW + (size_t)h * WW;
    for (int i = wid; i < 64; i += 8) {
        const float4* xr = (const float4*)(x + xbase + (size_t)i * HH * WW);
        float4 A4 = xr[lane];
        float4 B4 = xr[63 - lane];
        float m0 = __shfl_up_sync(0xffffffffu, B4.x, 1);
        float4 u, v;
        if (lane == 0) { u.x = A4.x;      v.x = 0.0f; }
        else           { u.x = A4.x + m0; v.x = A4.x - m0; }
        u.y = A4.y + B4.w;  v.y = A4.y - B4.w;
        u.z = A4.z + B4.z;  v.z = A4.z - B4.z;
        u.w = A4.w + B4.y;  v.w = A4.w - B4.y;
        *(float4*)&U[i*132 + 4*lane] = u;
        *(float4*)&V[i*132 + 4*lane] = v;
        if (lane == 31) U[i*132 + 128] = B4.x;
    }
    __syncthreads();

    int i0 = (tid >> 4) << 2;
    int l0 = (tid & 15) << 1;
    float re[4][2], im[4][2];
#pragma unroll
    for (int r = 0; r < 4; r++) { re[r][0]=re[r][1]=im[r][0]=im[r][1]=0.0f; }

    const float* U0  = U + i0*132;
    const float* V0  = V + i0*132;
    const float* Tcp = Tc + l0;
    const float* Tsp = Ts + l0;
#pragma unroll 3
    for (int w = 0; w < 129; w++) {
        float2 c = *(const float2*)&Tcp[w*34];
        float u0 = U0[w], u1 = U0[132+w], u2 = U0[264+w], u3 = U0[396+w];
        re[0][0] += u0*c.x; re[0][1] += u0*c.y;
        re[1][0] += u1*c.x; re[1][1] += u1*c.y;
        re[2][0] += u2*c.x; re[2][1] += u2*c.y;
        re[3][0] += u3*c.x; re[3][1] += u3*c.y;
    }
#pragma unroll 4
    for (int w = 0; w < 128; w++) {
        float2 s = *(const float2*)&Tsp[w*34];
        float v0 = V0[w], v1 = V0[132+w], v2 = V0[264+w], v3 = V0[396+w];
        im[0][0] += v0*s.x; im[0][1] += v0*s.y;
        im[1][0] += v1*s.x; im[1][1] += v1*s.y;
        im[2][0] += v2*s.x; im[2][1] += v2*s.y;
        im[3][0] += v3*s.x; im[3][1] += v3*s.y;
    }
#pragma unroll
    for (int r = 0; r < 4; r++) {
        size_t idx = (((size_t)(b*64 + i0 + r) * 256 + h) * 64) + 2*l0;
        *(float4*)&g_Xw[idx] = make_float4(re[r][0], im[r][0], re[r][1], im[r][1]);
    }
}

// ---------------------------------------------------------------------------
// Stage B: Xm[b,i,k,l] = sum_h Xw[b,i,h,l] * e^{-2*pi*i*k*h/256}
// ---------------------------------------------------------------------------
__global__ __launch_bounds__(256) void stageB() {
    __shared__ float2 tw[256];
    int tid = threadIdx.x;
    { float s, c; sincosf(6.283185307179586f * (float)tid * (1.0f/256.0f), &s, &c);
      tw[tid] = make_float2(c, s); }
    __syncthreads();
    int blk = blockIdx.x;                             // b*64+i
    const float2* Xp = (const float2*)(g_Xw) + (size_t)blk * HH * M1;
    int l  = tid & 31;
    int k0 = tid >> 5;
    float2 acc[4];
    int mt[4];
#pragma unroll
    for (int t = 0; t < 4; t++) { acc[t] = make_float2(0.f, 0.f); mt[t] = 0; }
    for (int h = 0; h < HH; h++) {
        float2 xv = Xp[h*M1 + l];
#pragma unroll
        for (int t = 0; t < 4; t++) {
            float2 e = tw[mt[t]];
            acc[t].x += xv.x*e.x + xv.y*e.y;          // (xr+ixi)*(c - i s)
            acc[t].y += xv.y*e.x - xv.x*e.y;
            mt[t] = (mt[t] + k0 + (t << 3)) & 255;
        }
    }
    float2* Om = (float2*)g_Xm + (size_t)blk * (M0*M1);
#pragma unroll
    for (int t = 0; t < 4; t++) {
        int k = k0 + (t << 3);
        Om[k*M1 + l] = acc[t];
    }
}

// ---------------------------------------------------------------------------
// Mode mix + gamma fold. W read coalesced from pre-transposed g_Wt[kl][p].
// ---------------------------------------------------------------------------
__global__ __launch_bounds__(256) void mixK() {
    __shared__ float2 Wsh[CI*CO];    // 32 KB
    __shared__ float2 Xsh[NB*CI];    //  8 KB
    int kl = blockIdx.x;
    int tid = threadIdx.x;
    const float4* wsrc = (const float4*)(g_Wt + (size_t)kl * 4096);
    for (int q = tid; q < 2048; q += 256)
        ((float4*)Wsh)[q] = wsrc[q];                  // coalesced 16B
    for (int p = tid; p < NB*CI; p += 256)
        Xsh[p] = ((const float2*)g_Xm)[(size_t)p*1024 + kl];
    __syncthreads();
#pragma unroll
    for (int q = 0; q < 4; q++) {
        int idx = tid + q*256;                        // b*64+o
        int b = idx >> 6, o = idx & 63;
        float yr = 0.f, yi = 0.f;
#pragma unroll 8
        for (int i = 0; i < CI; i++) {
            float2 xv = Xsh[(b << 6) + i];
            float2 wv = Wsh[(i << 6) + o];
            yr += xv.x*wv.x - xv.y*wv.y;
            yi += xv.x*wv.y + xv.y*wv.x;
        }
        float g = 1.0f + g_gamma[idx];
        ((float2*)g_Yb)[(size_t)idx*1024 + kl] = make_float2(g*yr, g*yi);
    }
}

// ---------------------------------------------------------------------------
// Stage C: Z[b,o,h,l] = sum_{k<32} Y[b,o,k,l] * e^{+2*pi*i*k*h/256}
// ---------------------------------------------------------------------------
__global__ __launch_bounds__(256) void stageC() {
    __shared__ float2 tw[256];
    int tid = threadIdx.x;
    { float s, c; sincosf(6.283185307179586f * (float)tid * (1.0f/256.0f), &s, &c);
      tw[tid] = make_float2(c, s); }
    __syncthreads();
    int blk = blockIdx.x;                             // b*64+o
    const float2* Yp = (const float2*)g_Yb + (size_t)blk * (M0*M1);
    int l  = tid & 31;
    int h0 = tid >> 5;
    float2 acc[32];
#pragma unroll
    for (int t = 0; t < 32; t++) acc[t] = make_float2(0.f, 0.f);
    for (int k = 0; k < M0; k++) {
        float2 yv = Yp[k*M1 + l];
        int mm = (k * h0) & 255;
        int st = (k << 3) & 255;
#pragma unroll
        for (int t = 0; t < 32; t++) {
            float2 e = tw[mm];
            acc[t].x += yv.x*e.x - yv.y*e.y;
            acc[t].y += yv.x*e.y + yv.y*e.x;
            mm = (mm + st) & 255;
        }
    }
    float2* Zp = (float2*)g_Z + (size_t)blk * HH * M1;
#pragma unroll
    for (int t = 0; t < 32; t++)
        Zp[(h0 + (t << 3))*M1 + l] = acc[t];
}

// ---------------------------------------------------------------------------
// Fused inverse-w DFT + FiLM beta + bypass 1x1 conv + GELU, SPLIT over o.
// Block = (b, h, o-half); thread owns column w=tid; acc[32] only.
// ~75 regs -> guaranteed no spill, 2 CTAs/SM (83KB smem).
// ---------------------------------------------------------------------------
#define ZP2 36
__global__ __launch_bounds__(256) void specfinal2K(const float* __restrict__ x,
                                                   const float* __restrict__ bw,
                                                   const float* __restrict__ bb,
                                                   float* __restrict__ out) {
    extern __shared__ float sm[];
    float* tinv_s = sm;                       // [64][256] 16384
    float* zzs    = sm + 16384;               // [64][ZP2]  2304
    float* bwsh   = zzs + 64*ZP2;             // [32][64]   2048
    float* beta_s = bwsh + 2048;              // [32]
    int tid = threadIdx.x;
    int b     = blockIdx.x >> 9;
    int h     = (blockIdx.x >> 1) & 255;
    int obase = (blockIdx.x & 1) << 5;        // 0 or 32

    for (int p = tid; p < 4096; p += 256)
        *(float4*)&tinv_s[p << 2] = *(const float4*)&g_Tinv[p << 2];
    for (int p = tid; p < 512; p += 256)
        *(float4*)&bwsh[p << 2] = *(const float4*)&bw[(obase << 6) + (p << 2)];
    // zz fill: coalesced Z read (l fastest), transposed store [l'][o2]
    for (int p = tid; p < 1024; p += 256) {
        int o2 = p >> 5, l = p & 31;
        float2 v = ((const float2*)g_Z)[((size_t)(b*64 + obase + o2) * 256 + h) * 32 + l];
        zzs[(2*l  )*ZP2 + o2] = v.x;
        zzs[(2*l+1)*ZP2 + o2] = v.y;
    }
    if (tid < 32) beta_s[tid] = g_beta[b*64 + obase + tid] + bb[obase + tid];
    __syncthreads();

    float acc[32];
#pragma unroll
    for (int o = 0; o < 32; o++) acc[o] = 0.0f;

    // Kick off first bypass channel loads; they complete under spectral FFMA.
    size_t xb = (size_t)b * CI * HH * WW + (size_t)h * WW + tid;
    float creg[8];
#pragma unroll
    for (int j = 0; j < 8; j++) creg[j] = x[xb + (size_t)j * HH * WW];

    // Spectral: acc[o2] += ZZ[l'][o2] * Tinv[l'][w]   (2048 FFMA)
    const float* tp = tinv_s + tid;
#pragma unroll 4
    for (int lp = 0; lp < 64; lp++) {
        float tv = tp[lp << 8];                      // conflict-free column read
        const float* zr = zzs + lp * ZP2;
#pragma unroll
        for (int og = 0; og < 8; og++) {
            float4 z = *(const float4*)&zr[og << 2]; // broadcast
            acc[4*og+0] += z.x * tv;
            acc[4*og+1] += z.y * tv;
            acc[4*og+2] += z.z * tv;
            acc[4*og+3] += z.w * tv;
        }
    }

    // Bypass: acc[o2] += sum_i bw[obase+o2][i] * x[b,i,h,w]  (2048 FFMA)
    for (int i = 0; i < CI; i += 8) {
        float nreg[8];
        if (i + 8 < CI) {
#pragma unroll
            for (int j = 0; j < 8; j++)
                nreg[j] = x[xb + (size_t)(i + 8 + j) * HH * WW];
        }
#pragma unroll
        for (int o = 0; o < 32; o++) {
            float4 wa = *(const float4*)&bwsh[(o << 6) + i];     // warp-uniform
            float4 wb = *(const float4*)&bwsh[(o << 6) + i + 4];
            acc[o] += wa.x*creg[0] + wa.y*creg[1] + wa.z*creg[2] + wa.w*creg[3]
                    + wb.x*creg[4] + wb.y*creg[5] + wb.z*creg[6] + wb.w*creg[7];
        }
#pragma unroll
        for (int j = 0; j < 8; j++) creg[j] = nreg[j];
    }

    size_t ob = (size_t)b * CO * HH * WW + (size_t)obase * HH * WW
              + (size_t)h * WW + tid;
#pragma unroll 8
    for (int o = 0; o < 32; o++)
        out[ob + (size_t)o * HH * WW] = gelu_tanh(acc[o] + beta_s[o]);
}

// ---------------------------------------------------------------------------
extern "C" void kernel_launch(void* const* d_in, const int* in_sizes, int n_in,
                              void* d_out, int out_size) {
    const float* x      = (const float*)d_in[0];
    const float* t_emb  = (const float*)d_in[1];
    const float* w_real = (const float*)d_in[2];
    const float* w_imag = (const float*)d_in[3];
    const float* fw1    = (const float*)d_in[4];
    const float* fb1    = (const float*)d_in[5];
    const float* fw2    = (const float*)d_in[6];
    const float* fb2    = (const float*)d_in[7];
    const float* bw     = (const float*)d_in[8];
    const float* bb     = (const float*)d_in[9];
    float* out = (float*)d_out;

    const int smemA = A3_SMEM * sizeof(float);                        // 102536
    const int smemF = (16384 + 64*ZP2 + 2048 + 32) * sizeof(float);   //  83072
    cudaFuncSetAttribute(stageA3,     cudaFuncAttributeMaxDynamicSharedMemorySize, smemA);
    cudaFuncSetAttribute(specfinal2K, cudaFuncAttributeMaxDynamicSharedMemorySize, smemF);

    setupK<<<4096, 256>>>(w_real, w_imag, t_emb, fw1, fb1, fw2, fb2); // 1
    stageA3<<<NB*HH, 256, smemA>>>(x);                                // 2
    stageB<<<NB*CI, 256>>>();                                         // 3
    mixK<<<M0*M1, 256>>>();                                           // 4 <- profiled
    stageC<<<NB*CO, 256>>>();                                         // 5
    specfinal2K<<<NB*HH*2, 256, smemF>>>(x, bw, bb, out);             // 6
}

// round 11
// speedup vs baseline: 1.7468x; 1.2295x over previous
#include <cuda_runtime.h>
#include <math.h>

// Shapes (fixed for this problem)
#define NB 16
#define CI 64
#define CO 64
#define HH 256
#define WW 256
#define M0 32
#define M1 32

typedef unsigned long long u64;

// Scratch (device globals; no allocation allowed in kernel_launch)
__device__ __align__(256) float g_Xw [(size_t)NB*CI*HH*M1*2]; // 67 MB  [b][i][h][l]{re,im}
__device__ __align__(256) float g_Xm [(size_t)NB*CI*M0*M1*2]; // 8.4 MB [b][i][k*32+l]{re,im}
__device__ __align__(256) float g_Yb [(size_t)NB*CO*M0*M1*2]; // 8.4 MB [b][o][k*32+l]{re,im}
__device__ __align__(256) float g_Z  [(size_t)NB*CO*HH*M1*2]; // 67 MB  [b][o][h][l]{re,im}
__device__ __align__(256) float2 g_Wt[(size_t)M0*M1*CI*CO];   // 33.5MB [kl][i*64+o]{re,im}
__device__ __align__(256) float g_Tfwd[WW*M1*2];              // forward DFT-w matrix [w][2l|2l+1]
__device__ __align__(256) float g_Tinv[M1*2*WW];              // inverse DFT-w matrix [2l|2l+1][w]
__device__ __align__(256) float g_gamma[NB*CO];
__device__ __align__(256) float g_beta [NB*CO];

// ---- packed fp32x2 helpers (SASS FFMA2 path; PTX-only, ptxas won't emit) ----
__device__ __forceinline__ u64 pack2(float lo, float hi) {
    u64 r; asm("mov.b64 %0, {%1, %2};" : "=l"(r) : "f"(lo), "f"(hi)); return r;
}
__device__ __forceinline__ u64 dup2(float v) { return pack2(v, v); }
__device__ __forceinline__ void fma2(u64 &d, u64 a, u64 b) {
    asm("fma.rn.f32x2 %0, %1, %2, %0;" : "+l"(d) : "l"(a), "l"(b));
}
__device__ __forceinline__ u64 add2(u64 a, u64 b) {
    u64 r; asm("add.rn.f32x2 %0, %1, %2;" : "=l"(r) : "l"(a), "l"(b)); return r;
}
__device__ __forceinline__ float2 unpk2(u64 v) {
    float2 f; asm("mov.b64 {%0, %1}, %2;" : "=f"(f.x), "=f"(f.y) : "l"(v)); return f;
}

__device__ __forceinline__ float gelu_tanh(float x) {
    float u = 0.7978845608028654f * (x + 0.044715f * x * x * x);
    float t;
    asm("tanh.approx.f32 %0, %1;" : "=f"(t) : "f"(u));
    return 0.5f * x * (1.0f + t);
}

// ---------------------------------------------------------------------------
// setupK (grid 4096, 256 thr): W transpose + DFT tables + FiLM.
// ---------------------------------------------------------------------------
__global__ __launch_bounds__(256) void setupK(const float* __restrict__ wr,
                                              const float* __restrict__ wi,
                                              const float* __restrict__ t_emb,
                                              const float* __restrict__ w1,
                                              const float* __restrict__ b1,
                                              const float* __restrict__ w2,
                                              const float* __restrict__ b2) {
    __shared__ float tr[32][33];
    __shared__ float ti[32][33];
    int tid = threadIdx.x;
    int p0  = (blockIdx.x >> 5) << 5;     // 128 p-tiles
    int kl0 = (blockIdx.x & 31) << 5;     // 32 kl-tiles
    {
        int c = tid & 31;
#pragma unroll
        for (int pass = 0; pass < 4; pass++) {
            int r = (tid >> 5) + (pass << 3);
            tr[r][c] = wr[(size_t)(p0 + r) * 1024 + kl0 + c];
            ti[r][c] = wi[(size_t)(p0 + r) * 1024 + kl0 + c];
        }
        __syncthreads();
#pragma unroll
        for (int pass = 0; pass < 4; pass++) {
            int r = (tid >> 5) + (pass << 3);
            g_Wt[(size_t)(kl0 + r) * 4096 + p0 + c] = make_float2(tr[c][r], ti[c][r]);
        }
    }

    if (blockIdx.x < 32) {
        int p = blockIdx.x * 256 + tid;   // 0..8191
        const float TWO_PI = 6.283185307179586f;
        {   // Forward table
            int w = p >> 5, l = p & 31;
            int m = (w * l) & 255;
            float s, c; sincosf(TWO_PI * (float)m * (1.0f/256.0f), &s, &c);
            g_Tfwd[w*64 + 2*l    ] =  c;
            g_Tfwd[w*64 + 2*l + 1] = -s;
        }
        {   // Inverse table, full ortho norm folded
            const float norm = 1.0f / 65536.0f;
            int l = p >> 8, w = p & 255;
            int m = (l * w) & 255;
            float s, c; sincosf(TWO_PI * (float)m * (1.0f/256.0f), &s, &c);
            g_Tinv[(2*l  )*WW + w] = norm * (l ? 2.0f : 1.0f) * c;
            g_Tinv[(2*l+1)*WW + w] = l ? (-2.0f * norm * s) : 0.0f;
        }
    }

    if (blockIdx.x == 4095) {             // FiLM
        __shared__ float tsh[NB*CI];
        __shared__ float hsh[NB*CI];
        __syncthreads();
        for (int p = tid; p < NB*CI; p += 256) tsh[p] = t_emb[p];
        __syncthreads();
        for (int p = tid; p < NB*CI; p += 256) {
            int b = p >> 6, j = p & 63;
            float s = b1[j];
            for (int i = 0; i < CI; i++) s += tsh[(b<<6)+i] * w1[i*CI + j];
            hsh[p] = s / (1.0f + expf(-s));
        }
        __syncthreads();
        for (int p = tid; p < NB*2*CO; p += 256) {
            int b = p >> 7, j = p & 127;
            float s = b2[j];
            for (int i = 0; i < CI; i++) s += hsh[(b<<6)+i] * w2[i*(2*CO) + j];
            if (j < CO) g_gamma[(b<<6)+j] = s;
            else        g_beta [(b<<6)+j-CO] = s;
        }
    }
}

// ---------------------------------------------------------------------------
// Stage A with real-input symmetry (halved FMA). One block per (b,h).
// ---------------------------------------------------------------------------
#define A3_U   0
#define A3_V   8448      // 64*132
#define A3_TC  16896
#define A3_TS  21282     // 16896 + 129*34
#define A3_SMEM (21282 + 128*34)   // 25634 floats

__global__ __launch_bounds__(256) void stageA3(const float* __restrict__ x) {
    extern __shared__ float sm[];
    float* U  = sm + A3_U;
    float* V  = sm + A3_V;
    float* Tc = sm + A3_TC;
    float* Ts = sm + A3_TS;
    int tid = threadIdx.x, lane = tid & 31, wid = tid >> 5;
    int b = blockIdx.x >> 8;
    int h = blockIdx.x & 255;

    for (int p = tid; p < 129*32; p += 256) {
        int w = p >> 5, l = p & 31;
        float2 cs = *(const float2*)&g_Tfwd[w*64 + 2*l];
        Tc[w*34 + l] = cs.x;
        if (w < 128) Ts[w*34 + l] = cs.y;
    }

    size_t xbase = (size_t)b * CI * HH * WW + (size_t)h * WW;
    for (int i = wid; i < 64; i += 8) {
        const float4* xr = (const float4*)(x + xbase + (size_t)i * HH * WW);
        float4 A4 = xr[lane];
        float4 B4 = xr[63 - lane];
        float m0 = __shfl_up_sync(0xffffffffu, B4.x, 1);
        float4 u, v;
        if (lane == 0) { u.x = A4.x;      v.x = 0.0f; }
        else           { u.x = A4.x + m0; v.x = A4.x - m0; }
        u.y = A4.y + B4.w;  v.y = A4.y - B4.w;
        u.z = A4.z + B4.z;  v.z = A4.z - B4.z;
        u.w = A4.w + B4.y;  v.w = A4.w - B4.y;
        *(float4*)&U[i*132 + 4*lane] = u;
        *(float4*)&V[i*132 + 4*lane] = v;
        if (lane == 31) U[i*132 + 128] = B4.x;
    }
    __syncthreads();

    int i0 = (tid >> 4) << 2;
    int l0 = (tid & 15) << 1;
    float re[4][2], im[4][2];
#pragma unroll
    for (int r = 0; r < 4; r++) { re[r][0]=re[r][1]=im[r][0]=im[r][1]=0.0f; }

    const float* U0  = U + i0*132;
    const float* V0  = V + i0*132;
    const float* Tcp = Tc + l0;
    const float* Tsp = Ts + l0;
#pragma unroll 3
    for (int w = 0; w < 129; w++) {
        float2 c = *(float2*)&Tcp[w*34];
        float u0 = U0[w], u1 = U0[132+w], u2 = U0[264+w], u3 = U0[396+w];
        re[0][0] += u0*c.x; re[0][1] += u0*c.y;
        re[1][0] += u1*c.x; re[1][1] += u1*c.y;
        re[2][0] += u2*c.x; re[2][1] += u2*c.y;
        re[3][0] += u3*c.x; re[3][1] += u3*c.y;
    }
#pragma unroll 4
    for (int w = 0; w < 128; w++) {
        float2 s = *(float2*)&Tsp[w*34];
        float v0 = V0[w], v1 = V0[132+w], v2 = V0[264+w], v3 = V0[396+w];
        im[0][0] += v0*s.x; im[0][1] += v0*s.y;
        im[1][0] += v1*s.x; im[1][1] += v1*s.y;
        im[2][0] += v2*s.x; im[2][1] += v2*s.y;
        im[3][0] += v3*s.x; im[3][1] += v3*s.y;
    }
#pragma unroll
    for (int r = 0; r < 4; r++) {
        size_t idx = (((size_t)(b*64 + i0 + r) * 256 + h) * 64) + 2*l0;
        *(float4*)&g_Xw[idx] = make_float4(re[r][0], im[r][0], re[r][1], im[r][1]);
    }
}

// ---------------------------------------------------------------------------
// Stage B: Xm[b,i,k,l] = sum_h Xw[b,i,h,l] * e^{-2*pi*i*k*h/256}
// ---------------------------------------------------------------------------
__global__ __launch_bounds__(256) void stageB() {
    __shared__ float2 tw[256];
    int tid = threadIdx.x;
    { float s, c; sincosf(6.283185307179586f * (float)tid * (1.0f/256.0f), &s, &c);
      tw[tid] = make_float2(c, s); }
    __syncthreads();
    int blk = blockIdx.x;                             // b*64+i
    const float2* Xp = (const float2*)(g_Xw) + (size_t)blk * HH * M1;
    int l  = tid & 31;
    int k0 = tid >> 5;
    float2 acc[4];
    int mt[4];
#pragma unroll
    for (int t = 0; t < 4; t++) { acc[t] = make_float2(0.f, 0.f); mt[t] = 0; }
    for (int h = 0; h < HH; h++) {
        float2 xv = Xp[h*M1 + l];
#pragma unroll
        for (int t = 0; t < 4; t++) {
            float2 e = tw[mt[t]];
            acc[t].x += xv.x*e.x + xv.y*e.y;          // (xr+ixi)*(c - i s)
            acc[t].y += xv.y*e.x - xv.x*e.y;
            mt[t] = (mt[t] + k0 + (t << 3)) & 255;
        }
    }
    float2* Om = (float2*)g_Xm + (size_t)blk * (M0*M1);
#pragma unroll
    for (int t = 0; t < 4; t++) {
        int k = k0 + (t << 3);
        Om[k*M1 + l] = acc[t];
    }
}

// ---------------------------------------------------------------------------
// Mode mix + gamma fold. W read coalesced from pre-transposed g_Wt[kl][p].
// ---------------------------------------------------------------------------
__global__ __launch_bounds__(256) void mixK() {
    __shared__ float2 Wsh[CI*CO];    // 32 KB
    __shared__ float2 Xsh[NB*CI];    //  8 KB
    int kl = blockIdx.x;
    int tid = threadIdx.x;
    const float4* wsrc = (const float4*)(g_Wt + (size_t)kl * 4096);
    for (int q = tid; q < 2048; q += 256)
        ((float4*)Wsh)[q] = wsrc[q];                  // coalesced 16B
    for (int p = tid; p < NB*CI; p += 256)
        Xsh[p] = ((const float2*)g_Xm)[(size_t)p*1024 + kl];
    __syncthreads();
#pragma unroll
    for (int q = 0; q < 4; q++) {
        int idx = tid + q*256;                        // b*64+o
        int b = idx >> 6, o = idx & 63;
        float yr = 0.f, yi = 0.f;
#pragma unroll 8
        for (int i = 0; i < CI; i++) {
            float2 xv = Xsh[(b << 6) + i];
            float2 wv = Wsh[(i << 6) + o];
            yr += xv.x*wv.x - xv.y*wv.y;
            yi += xv.x*wv.y + xv.y*wv.x;
        }
        float g = 1.0f + g_gamma[idx];
        ((float2*)g_Yb)[(size_t)idx*1024 + kl] = make_float2(g*yr, g*yi);
    }
}

// ---------------------------------------------------------------------------
// Stage C (f32x2): Z[b,o,h,l] = sum_k Y[b,o,k,l] * e^{+i th k h}
// Paired twiddle table {(c,s),(-s,c)}: one LDS.128 broadcast + 2 FFMA2/step.
// ---------------------------------------------------------------------------
__global__ __launch_bounds__(256) void stageC() {
    __shared__ ulonglong2 twp[256];   // 4 KB
    int tid = threadIdx.x;
    { float s, c; sincosf(6.283185307179586f * (float)tid * (1.0f/256.0f), &s, &c);
      twp[tid] = make_ulonglong2(pack2(c, s), pack2(-s, c)); }
    __syncthreads();
    int blk = blockIdx.x;                             // b*64+o
    const float2* Yp = (const float2*)g_Yb + (size_t)blk * (M0*M1);
    int l  = tid & 31;
    int h0 = tid >> 5;
    u64 acc2[32];
#pragma unroll
    for (int t = 0; t < 32; t++) acc2[t] = 0ULL;
    for (int k = 0; k < M0; k++) {
        float2 yv = Yp[k*M1 + l];
        u64 yr2 = dup2(yv.x), yi2 = dup2(yv.y);
        int mm = (k * h0) & 255;
        int st = (k << 3) & 255;
#pragma unroll
        for (int t = 0; t < 32; t++) {
            ulonglong2 e = twp[mm];                   // warp-uniform broadcast
            fma2(acc2[t], e.x, yr2);                  // (.x+=c*yr, .y+=s*yr)
            fma2(acc2[t], e.y, yi2);                  // (.x+=-s*yi,.y+=c*yi)
            mm = (mm + st) & 255;
        }
    }
    float2* Zp = (float2*)g_Z + (size_t)blk * HH * M1;
#pragma unroll
    for (int t = 0; t < 32; t++)
        Zp[(h0 + (t << 3))*M1 + l] = unpk2(acc2[t]);
}

// ---------------------------------------------------------------------------
// Fused inverse-w DFT + beta + bypass + GELU, split over o, f32x2 math.
// Block = (b, h, o-half); thread owns w=tid; acc2[16] u64 = 32 fp32 accs.
// ---------------------------------------------------------------------------
#define ZP2 36
__global__ __launch_bounds__(256) void specfinal3K(const float* __restrict__ x,
                                                   const float* __restrict__ bw,
                                                   const float* __restrict__ bb,
                                                   float* __restrict__ out) {
    extern __shared__ float sm[];
    float* tinv_s = sm;                       // [64][256] 16384 floats
    float* zzs    = sm + 16384;               // [64][ZP2]  2304
    float* bwt    = zzs + 64*ZP2;             // [64][32] transposed, 2048
    float* beta_s = bwt + 2048;               // [32]
    int tid = threadIdx.x;
    int b     = blockIdx.x >> 9;
    int h     = (blockIdx.x >> 1) & 255;
    int obase = (blockIdx.x & 1) << 5;        // 0 or 32

    for (int p = tid; p < 4096; p += 256)
        *(float4*)&tinv_s[p << 2] = *(const float4*)&g_Tinv[p << 2];
    // bw transposed into [i][o2] so o-pairs are adjacent (bw is 16KB -> L1-hot)
    for (int p = tid; p < 2048; p += 256) {
        int i = p >> 5, o2 = p & 31;
        bwt[p] = bw[(size_t)(obase + o2) * 64 + i];
    }
    // zz fill: coalesced Z read (l fastest), transposed store [l'][o2]
    for (int p = tid; p < 1024; p += 256) {
        int o2 = p >> 5, l = p & 31;
        float2 v = ((const float2*)g_Z)[((size_t)(b*64 + obase + o2) * 256 + h) * 32 + l];
        zzs[(2*l  )*ZP2 + o2] = v.x;
        zzs[(2*l+1)*ZP2 + o2] = v.y;
    }
    if (tid < 32) beta_s[tid] = g_beta[b*64 + obase + tid] + bb[obase + tid];
    __syncthreads();

    u64 acc2[16];
#pragma unroll
    for (int p = 0; p < 16; p++) acc2[p] = 0ULL;

    // Kick off first bypass channel loads; they complete under spectral FFMA.
    size_t xb = (size_t)b * CI * HH * WW + (size_t)h * WW + tid;
    float creg[8];
#pragma unroll
    for (int j = 0; j < 8; j++) creg[j] = x[xb + (size_t)j * HH * WW];

    // Spectral: acc2 += pack(zz[lp][2p],zz[lp][2p+1]) * dup(Tinv[lp][w])
    const float* tp = tinv_s + tid;
#pragma unroll 4
    for (int lp = 0; lp < 64; lp++) {
        u64 td = dup2(tp[lp << 8]);               // conflict-free column read
        const ulonglong2* zr = (const ulonglong2*)(zzs + lp * ZP2);
#pragma unroll
        for (int og = 0; og < 8; og++) {
            ulonglong2 zp = zr[og];               // LDS.128 broadcast
            fma2(acc2[2*og    ], zp.x, td);
            fma2(acc2[2*og + 1], zp.y, td);
        }
    }

    // Bypass: acc2 += pack(bw[i][2p],bw[i][2p+1]) * dup(x[b,i,h,w])
    for (int i = 0; i < CI; i += 8) {
        float nreg[8];
        if (i + 8 < CI) {
#pragma unroll
            for (int j = 0; j < 8; j++)
                nreg[j] = x[xb + (size_t)(i + 8 + j) * HH * WW];
        }
#pragma unroll
        for (int j = 0; j < 8; j++) {
            u64 xd = dup2(creg[j]);
            const ulonglong2* wr2 = (const ulonglong2*)(bwt + ((i + j) << 5));
#pragma unroll
            for (int og = 0; og < 8; og++) {
                ulonglong2 wp = wr2[og];          // LDS.128 broadcast
                fma2(acc2[2*og    ], wp.x, xd);
                fma2(acc2[2*og + 1], wp.y, xd);
            }
        }
#pragma unroll
        for (int j = 0; j < 8; j++) creg[j] = nreg[j];
    }

    size_t ob = (size_t)b * CO * HH * WW + (size_t)obase * HH * WW
              + (size_t)h * WW + tid;
#pragma unroll 8
    for (int p = 0; p < 16; p++) {
        u64 bpair = *(const u64*)&beta_s[p << 1];
        float2 v = unpk2(add2(acc2[p], bpair));
        out[ob + (size_t)(2*p    ) * HH * WW] = gelu_tanh(v.x);
        out[ob + (size_t)(2*p + 1) * HH * WW] = gelu_tanh(v.y);
    }
}

// ---------------------------------------------------------------------------
extern "C" void kernel_launch(void* const* d_in, const int* in_sizes, int n_in,
                              void* d_out, int out_size) {
    const float* x      = (const float*)d_in[0];
    const float* t_emb  = (const float*)d_in[1];
    const float* w_real = (const float*)d_in[2];
    const float* w_imag = (const float*)d_in[3];
    const float* fw1    = (const float*)d_in[4];
    const float* fb1    = (const float*)d_in[5];
    const float* fw2    = (const float*)d_in[6];
    const float* fb2    = (const float*)d_in[7];
    const float* bw     = (const float*)d_in[8];
    const float* bb     = (const float*)d_in[9];
    float* out = (float*)d_out;

    const int smemA = A3_SMEM * sizeof(float);                        // 102536
    const int smemF = (16384 + 64*ZP2 + 2048 + 32) * sizeof(float);   //  83072
    cudaFuncSetAttribute(stageA3,     cudaFuncAttributeMaxDynamicSharedMemorySize, smemA);
    cudaFuncSetAttribute(specfinal3K, cudaFuncAttributeMaxDynamicSharedMemorySize, smemF);

    setupK<<<4096, 256>>>(w_real, w_imag, t_emb, fw1, fb1, fw2, fb2); // 1
    stageA3<<<NB*HH, 256, smemA>>>(x);                                // 2
    stageB<<<NB*CI, 256>>>();                                         // 3
    mixK<<<M0*M1, 256>>>();                                           // 4 <- profiled
    stageC<<<NB*CO, 256>>>();                                         // 5
    specfinal3K<<<NB*HH*2, 256, smemF>>>(x, bw, bb, out);             // 6
}

// round 12
// speedup vs baseline: 1.9090x; 1.0928x over previous
#include <cuda_runtime.h>
#include <math.h>

// Shapes (fixed for this problem)
#define NB 16
#define CI 64
#define CO 64
#define HH 256
#define WW 256
#define M0 32
#define M1 32

typedef unsigned long long u64;

// Scratch (device globals; no allocation allowed in kernel_launch)
__device__ __align__(256) float g_Xw [(size_t)NB*CI*HH*M1*2]; // 67 MB  [b][i][h][l]{re,im}
__device__ __align__(256) float g_Xm [(size_t)NB*CI*M0*M1*2]; // 8.4 MB [b][i][k*32+l]{re,im}
__device__ __align__(256) float g_Yb [(size_t)NB*CO*M0*M1*2]; // 8.4 MB [b][o][k*32+l]{re,im}
__device__ __align__(256) float g_Z  [(size_t)NB*CO*HH*M1*2]; // 67 MB  [b][o][h][l]{re,im}
__device__ __align__(256) float2 g_Wt[(size_t)M0*M1*CI*CO];   // 33.5MB [kl][i*64+o]{re,im}
__device__ __align__(256) float g_Tfwd[WW*M1*2];              // forward DFT-w matrix [w][2l|2l+1]
__device__ __align__(256) float g_gamma[NB*CO];
__device__ __align__(256) float g_beta [NB*CO];

// ---- packed fp32x2 helpers (SASS FFMA2 path; PTX-only, ptxas won't emit) ----
__device__ __forceinline__ u64 pack2(float lo, float hi) {
    u64 r; asm("mov.b64 %0, {%1, %2};" : "=l"(r) : "f"(lo), "f"(hi)); return r;
}
__device__ __forceinline__ u64 dup2(float v) { return pack2(v, v); }
__device__ __forceinline__ void fma2(u64 &d, u64 a, u64 b) {
    asm("fma.rn.f32x2 %0, %1, %2, %0;" : "+l"(d) : "l"(a), "l"(b));
}
__device__ __forceinline__ u64 add2(u64 a, u64 b) {
    u64 r; asm("add.rn.f32x2 %0, %1, %2;" : "=l"(r) : "l"(a), "l"(b)); return r;
}
__device__ __forceinline__ float2 unpk2(u64 v) {
    float2 f; asm("mov.b64 {%0, %1}, %2;" : "=f"(f.x), "=f"(f.y) : "l"(v)); return f;
}

__device__ __forceinline__ float gelu_tanh(float x) {
    float u = 0.7978845608028654f * (x + 0.044715f * x * x * x);
    float t;
    asm("tanh.approx.f32 %0, %1;" : "=f"(t) : "f"(u));
    return 0.5f * x * (1.0f + t);
}

// ---------------------------------------------------------------------------
// setupK (grid 4096, 256 thr): W transpose + forward table + FiLM.
// (Inverse table no longer needed — specfinal generates it by recurrence.)
// ---------------------------------------------------------------------------
__global__ __launch_bounds__(256) void setupK(const float* __restrict__ wr,
                                              const float* __restrict__ wi,
                                              const float* __restrict__ t_emb,
                                              const float* __restrict__ w1,
                                              const float* __restrict__ b1,
                                              const float* __restrict__ w2,
                                              const float* __restrict__ b2) {
    __shared__ float tr[32][33];
    __shared__ float ti[32][33];
    int tid = threadIdx.x;
    int p0  = (blockIdx.x >> 5) << 5;     // 128 p-tiles
    int kl0 = (blockIdx.x & 31) << 5;     // 32 kl-tiles
    {
        int c = tid & 31;
#pragma unroll
        for (int pass = 0; pass < 4; pass++) {
            int r = (tid >> 5) + (pass << 3);
            tr[r][c] = wr[(size_t)(p0 + r) * 1024 + kl0 + c];
            ti[r][c] = wi[(size_t)(p0 + r) * 1024 + kl0 + c];
        }
        __syncthreads();
#pragma unroll
        for (int pass = 0; pass < 4; pass++) {
            int r = (tid >> 5) + (pass << 3);
            g_Wt[(size_t)(kl0 + r) * 4096 + p0 + c] = make_float2(tr[c][r], ti[c][r]);
        }
    }

    if (blockIdx.x < 32) {                // forward table
        int p = blockIdx.x * 256 + tid;   // 0..8191
        int w = p >> 5, l = p & 31;
        int m = (w * l) & 255;
        float s, c; sincosf(6.283185307179586f * (float)m * (1.0f/256.0f), &s, &c);
        g_Tfwd[w*64 + 2*l    ] =  c;
        g_Tfwd[w*64 + 2*l + 1] = -s;
    }

    if (blockIdx.x == 4095) {             // FiLM
        __shared__ float tsh[NB*CI];
        __shared__ float hsh[NB*CI];
        __syncthreads();
        for (int p = tid; p < NB*CI; p += 256) tsh[p] = t_emb[p];
        __syncthreads();
        for (int p = tid; p < NB*CI; p += 256) {
            int b = p >> 6, j = p & 63;
            float s = b1[j];
            for (int i = 0; i < CI; i++) s += tsh[(b<<6)+i] * w1[i*CI + j];
            hsh[p] = s / (1.0f + expf(-s));
        }
        __syncthreads();
        for (int p = tid; p < NB*2*CO; p += 256) {
            int b = p >> 7, j = p & 127;
            float s = b2[j];
            for (int i = 0; i < CI; i++) s += hsh[(b<<6)+i] * w2[i*(2*CO) + j];
            if (j < CO) g_gamma[(b<<6)+j] = s;
            else        g_beta [(b<<6)+j-CO] = s;
        }
    }
}

// ---------------------------------------------------------------------------
// Stage A with real-input symmetry (halved FMA). One block per (b,h).
// ---------------------------------------------------------------------------
#define A3_U   0
#define A3_V   8448      // 64*132
#define A3_TC  16896
#define A3_TS  21282     // 16896 + 129*34
#define A3_SMEM (21282 + 128*34)   // 25634 floats

__global__ __launch_bounds__(256) void stageA3(const float* __restrict__ x) {
    extern __shared__ float sm[];
    float* U  = sm + A3_U;
    float* V  = sm + A3_V;
    float* Tc = sm + A3_TC;
    float* Ts = sm + A3_TS;
    int tid = threadIdx.x, lane = tid & 31, wid = tid >> 5;
    int b = blockIdx.x >> 8;
    int h = blockIdx.x & 255;

    for (int p = tid; p < 129*32; p += 256) {
        int w = p >> 5, l = p & 31;
        float2 cs = *(const float2*)&g_Tfwd[w*64 + 2*l];
        Tc[w*34 + l] = cs.x;
        if (w < 128) Ts[w*34 + l] = cs.y;
    }

    size_t xbase = (size_t)b * CI * HH * WW + (size_t)h * WW;
    for (int i = wid; i < 64; i += 8) {
        const float4* xr = (const float4*)(x + xbase + (size_t)i * HH * WW);
        float4 A4 = xr[lane];
        float4 B4 = xr[63 - lane];
        float m0 = __shfl_up_sync(0xffffffffu, B4.x, 1);
        float4 u, v;
        if (lane == 0) { u.x = A4.x;      v.x = 0.0f; }
        else           { u.x = A4.x + m0; v.x = A4.x - m0; }
        u.y = A4.y + B4.w;  v.y = A4.y - B4.w;
        u.z = A4.z + B4.z;  v.z = A4.z - B4.z;
        u.w = A4.w + B4.y;  v.w = A4.w - B4.y;
        *(float4*)&U[i*132 + 4*lane] = u;
        *(float4*)&V[i*132 + 4*lane] = v;
        if (lane == 31) U[i*132 + 128] = B4.x;
    }
    __syncthreads();

    int i0 = (tid >> 4) << 2;
    int l0 = (tid & 15) << 1;
    float re[4][2], im[4][2];
#pragma unroll
    for (int r = 0; r < 4; r++) { re[r][0]=re[r][1]=im[r][0]=im[r][1]=0.0f; }

    const float* U0  = U + i0*132;
    const float* V0  = V + i0*132;
    const float* Tcp = Tc + l0;
    const float* Tsp = Ts + l0;
#pragma unroll 3
    for (int w = 0; w < 129; w++) {
        float2 c = *(float2*)&Tcp[w*34];
        float u0 = U0[w], u1 = U0[132+w], u2 = U0[264+w], u3 = U0[396+w];
        re[0][0] += u0*c.x; re[0][1] += u0*c.y;
        re[1][0] += u1*c.x; re[1][1] += u1*c.y;
        re[2][0] += u2*c.x; re[2][1] += u2*c.y;
        re[3][0] += u3*c.x; re[3][1] += u3*c.y;
    }
#pragma unroll 4
    for (int w = 0; w < 128; w++) {
        float2 s = *(float2*)&Tsp[w*34];
        float v0 = V0[w], v1 = V0[132+w], v2 = V0[264+w], v3 = V0[396+w];
        im[0][0] += v0*s.x; im[0][1] += v0*s.y;
        im[1][0] += v1*s.x; im[1][1] += v1*s.y;
        im[2][0] += v2*s.x; im[2][1] += v2*s.y;
        im[3][0] += v3*s.x; im[3][1] += v3*s.y;
    }
#pragma unroll
    for (int r = 0; r < 4; r++) {
        size_t idx = (((size_t)(b*64 + i0 + r) * 256 + h) * 64) + 2*l0;
        *(float4*)&g_Xw[idx] = make_float4(re[r][0], im[r][0], re[r][1], im[r][1]);
    }
}

// ---------------------------------------------------------------------------
// Stage B (f32x2): Xm[b,i,k,l] = sum_h Xw[b,i,h,l] * e^{-i th k h}
// Paired table {(c,-s),(s,c)}: acc(re,im) += {c,-s}*dup(xr) + {s,c}*dup(xi).
// mt[t] warp-uniform -> LDS.128 broadcast.
// ---------------------------------------------------------------------------
__global__ __launch_bounds__(256) void stageB() {
    __shared__ ulonglong2 twp[256];   // 4 KB
    int tid = threadIdx.x;
    { float s, c; sincosf(6.283185307179586f * (float)tid * (1.0f/256.0f), &s, &c);
      twp[tid] = make_ulonglong2(pack2(c, -s), pack2(s, c)); }
    __syncthreads();
    int blk = blockIdx.x;                             // b*64+i
    const float2* Xp = (const float2*)(g_Xw) + (size_t)blk * HH * M1;
    int l  = tid & 31;
    int k0 = tid >> 5;
    u64 acc2[4];
    int mt[4];
#pragma unroll
    for (int t = 0; t < 4; t++) { acc2[t] = 0ULL; mt[t] = 0; }
    for (int h = 0; h < HH; h++) {
        float2 xv = Xp[h*M1 + l];
        u64 xr2 = dup2(xv.x), xi2 = dup2(xv.y);
#pragma unroll
        for (int t = 0; t < 4; t++) {
            ulonglong2 e = twp[mt[t]];                // broadcast LDS.128
            fma2(acc2[t], e.x, xr2);
            fma2(acc2[t], e.y, xi2);
            mt[t] = (mt[t] + k0 + (t << 3)) & 255;
        }
    }
    float2* Om = (float2*)g_Xm + (size_t)blk * (M0*M1);
#pragma unroll
    for (int t = 0; t < 4; t++) {
        int k = k0 + (t << 3);
        Om[k*M1 + l] = unpk2(acc2[t]);
    }
}

// ---------------------------------------------------------------------------
// Mode mix + gamma fold. W read coalesced from pre-transposed g_Wt[kl][p].
// ---------------------------------------------------------------------------
__global__ __launch_bounds__(256) void mixK() {
    __shared__ float2 Wsh[CI*CO];    // 32 KB
    __shared__ float2 Xsh[NB*CI];    //  8 KB
    int kl = blockIdx.x;
    int tid = threadIdx.x;
    const float4* wsrc = (const float4*)(g_Wt + (size_t)kl * 4096);
    for (int q = tid; q < 2048; q += 256)
        ((float4*)Wsh)[q] = wsrc[q];                  // coalesced 16B
    for (int p = tid; p < NB*CI; p += 256)
        Xsh[p] = ((const float2*)g_Xm)[(size_t)p*1024 + kl];
    __syncthreads();
#pragma unroll
    for (int q = 0; q < 4; q++) {
        int idx = tid + q*256;                        // b*64+o
        int b = idx >> 6, o = idx & 63;
        float yr = 0.f, yi = 0.f;
#pragma unroll 8
        for (int i = 0; i < CI; i++) {
            float2 xv = Xsh[(b << 6) + i];
            float2 wv = Wsh[(i << 6) + o];
            yr += xv.x*wv.x - xv.y*wv.y;
            yi += xv.x*wv.y + xv.y*wv.x;
        }
        float g = 1.0f + g_gamma[idx];
        ((float2*)g_Yb)[(size_t)idx*1024 + kl] = make_float2(g*yr, g*yi);
    }
}

// ---------------------------------------------------------------------------
// Stage C (f32x2): Z[b,o,h,l] = sum_k Y[b,o,k,l] * e^{+i th k h}
// ---------------------------------------------------------------------------
__global__ __launch_bounds__(256) void stageC() {
    __shared__ ulonglong2 twp[256];   // 4 KB
    int tid = threadIdx.x;
    { float s, c; sincosf(6.283185307179586f * (float)tid * (1.0f/256.0f), &s, &c);
      twp[tid] = make_ulonglong2(pack2(c, s), pack2(-s, c)); }
    __syncthreads();
    int blk = blockIdx.x;                             // b*64+o
    const float2* Yp = (const float2*)g_Yb + (size_t)blk * (M0*M1);
    int l  = tid & 31;
    int h0 = tid >> 5;
    u64 acc2[32];
#pragma unroll
    for (int t = 0; t < 32; t++) acc2[t] = 0ULL;
    for (int k = 0; k < M0; k++) {
        float2 yv = Yp[k*M1 + l];
        u64 yr2 = dup2(yv.x), yi2 = dup2(yv.y);
        int mm = (k * h0) & 255;
        int st = (k << 3) & 255;
#pragma unroll
        for (int t = 0; t < 32; t++) {
            ulonglong2 e = twp[mm];                   // warp-uniform broadcast
            fma2(acc2[t], e.x, yr2);                  // (.x+=c*yr, .y+=s*yr)
            fma2(acc2[t], e.y, yi2);                  // (.x+=-s*yi,.y+=c*yi)
            mm = (mm + st) & 255;
        }
    }
    float2* Zp = (float2*)g_Z + (size_t)blk * HH * M1;
#pragma unroll
    for (int t = 0; t < 32; t++)
        Zp[(h0 + (t << 3))*M1 + l] = unpk2(acc2[t]);
}

// ---------------------------------------------------------------------------
// Fused inverse-w DFT + beta + bypass + GELU, split over o, f32x2 math,
// Tinv generated per-thread by rotation recurrence (no 64KB smem tile).
// spec[w] = sum_l zzRe[l]*cos(th l w) + zzIm[l]*sin(th l w),
//   zzRe = Z.re*(l?2:1)/65536, zzIm = -Z.im*2/65536 (ortho norm folded).
// smem 16.6KB, regs ~60 -> 3 CTAs/SM (6 warps/SMSP).
// ---------------------------------------------------------------------------
__global__ __launch_bounds__(256, 3) void specfinal4K(const float* __restrict__ x,
                                                      const float* __restrict__ bw,
                                                      const float* __restrict__ bb,
                                                      float* __restrict__ out) {
    __shared__ float zzRe[32*32];     // [l][o2] 4KB
    __shared__ float zzIm[32*32];     // [l][o2] 4KB
    __shared__ float bwt [64*32];     // [i][o2] 8KB
    __shared__ float beta_s[32];
    int tid = threadIdx.x;
    int b     = blockIdx.x >> 9;
    int h     = (blockIdx.x >> 1) & 255;
    int obase = (blockIdx.x & 1) << 5;        // 0 or 32

    // bw transposed into [i][o2] so o-pairs are adjacent
    for (int p = tid; p < 2048; p += 256) {
        int i = p >> 5, o2 = p & 31;
        bwt[p] = bw[(size_t)(obase + o2) * 64 + i];
    }
    // zz fill with norm folding; coalesced Z read (l fastest)
    const float nrm = 1.0f / 65536.0f;
    for (int p = tid; p < 1024; p += 256) {
        int o2 = p >> 5, l = p & 31;
        float2 v = ((const float2*)g_Z)[((size_t)(b*64 + obase + o2) * 256 + h) * 32 + l];
        zzRe[l*32 + o2] = v.x * (l ? 2.0f*nrm : nrm);
        zzIm[l*32 + o2] = v.y * (-2.0f*nrm);
    }
    if (tid < 32) beta_s[tid] = g_beta[b*64 + obase + tid] + bb[obase + tid];
    __syncthreads();

    u64 acc2[16];
#pragma unroll
    for (int p = 0; p < 16; p++) acc2[p] = 0ULL;

    // Kick off first bypass channel loads; they complete under spectral FFMA.
    size_t xb = (size_t)b * CI * HH * WW + (size_t)h * WW + tid;
    float creg[4];
#pragma unroll
    for (int j = 0; j < 4; j++) creg[j] = x[xb + (size_t)j * HH * WW];

    // Spectral with rotation recurrence: (c,s) = e^{i*2*pi*w*l/256}
    float cr, sr;
    sincosf(6.283185307179586f * (float)tid * (1.0f/256.0f), &sr, &cr);
    float c = 1.0f, s = 0.0f;
#pragma unroll 4
    for (int l = 0; l < 32; l++) {
        u64 cd = dup2(c), sd = dup2(s);
        const ulonglong2* zr = (const ulonglong2*)(zzRe + l*32);
        const ulonglong2* zi = (const ulonglong2*)(zzIm + l*32);
#pragma unroll
        for (int og = 0; og < 8; og++) {
            ulonglong2 zp = zr[og];               // LDS.128 broadcast
            fma2(acc2[2*og    ], zp.x, cd);
            fma2(acc2[2*og + 1], zp.y, cd);
            ulonglong2 ip = zi[og];
            fma2(acc2[2*og    ], ip.x, sd);
            fma2(acc2[2*og + 1], ip.y, sd);
        }
        float cn = c*cr - s*sr;
        float sn = s*cr + c*sr;
        c = cn; s = sn;
    }

    // Bypass: acc2 += pack(bw[i][2p],bw[i][2p+1]) * dup(x[b,i,h,w])
    for (int i = 0; i < CI; i += 4) {
        float nreg[4];
        if (i + 4 < CI) {
#pragma unroll
            for (int j = 0; j < 4; j++)
                nreg[j] = x[xb + (size_t)(i + 4 + j) * HH * WW];
        }
#pragma unroll
        for (int j = 0; j < 4; j++) {
            u64 xd = dup2(creg[j]);
            const ulonglong2* wr2 = (const ulonglong2*)(bwt + ((i + j) << 5));
#pragma unroll
            for (int og = 0; og < 8; og++) {
                ulonglong2 wp = wr2[og];          // LDS.128 broadcast
                fma2(acc2[2*og    ], wp.x, xd);
                fma2(acc2[2*og + 1], wp.y, xd);
            }
        }
#pragma unroll
        for (int j = 0; j < 4; j++) creg[j] = nreg[j];
    }

    size_t ob = (size_t)b * CO * HH * WW + (size_t)obase * HH * WW
              + (size_t)h * WW + tid;
#pragma unroll 8
    for (int p = 0; p < 16; p++) {
        u64 bpair = *(const u64*)&beta_s[p << 1];
        float2 v = unpk2(add2(acc2[p], bpair));
        out[ob + (size_t)(2*p    ) * HH * WW] = gelu_tanh(v.x);
        out[ob + (size_t)(2*p + 1) * HH * WW] = gelu_tanh(v.y);
    }
}

// ---------------------------------------------------------------------------
extern "C" void kernel_launch(void* const* d_in, const int* in_sizes, int n_in,
                              void* d_out, int out_size) {
    const float* x      = (const float*)d_in[0];
    const float* t_emb  = (const float*)d_in[1];
    const float* w_real = (const float*)d_in[2];
    const float* w_imag = (const float*)d_in[3];
    const float* fw1    = (const float*)d_in[4];
    const float* fb1    = (const float*)d_in[5];
    const float* fw2    = (const float*)d_in[6];
    const float* fb2    = (const float*)d_in[7];
    const float* bw     = (const float*)d_in[8];
    const float* bb     = (const float*)d_in[9];
    float* out = (float*)d_out;

    const int smemA = A3_SMEM * sizeof(float);                        // 102536
    cudaFuncSetAttribute(stageA3, cudaFuncAttributeMaxDynamicSharedMemorySize, smemA);

    setupK<<<4096, 256>>>(w_real, w_imag, t_emb, fw1, fb1, fw2, fb2); // 1
    stageA3<<<NB*HH, 256, smemA>>>(x);                                // 2
    stageB<<<NB*CI, 256>>>();                                         // 3
    mixK<<<M0*M1, 256>>>();                                           // 4 <- profiled
    stageC<<<NB*CO, 256>>>();                                         // 5
    specfinal4K<<<NB*HH*2, 256>>>(x, bw, bb, out);                    // 6
}

// round 13
// speedup vs baseline: 2.4906x; 1.3047x over previous
#include <cuda_runtime.h>
#include <math.h>

// Shapes (fixed for this problem)
#define NB 16
#define CI 64
#define CO 64
#define HH 256
#define WW 256
#define M0 32
#define M1 32

typedef unsigned long long u64;

// Scratch (device globals; no allocation allowed in kernel_launch)
__device__ __align__(256) float g_Xw [(size_t)NB*CI*HH*M1*2]; // 67 MB  [b][i][h][l]{re,im}
__device__ __align__(256) float g_Xm [(size_t)NB*CI*M0*M1*2]; // 8.4 MB [b][i][k*32+l]{re,im}
__device__ __align__(256) float g_Yb [(size_t)NB*CO*M0*M1*2]; // 8.4 MB [b][o][k*32+l]{re,im}
__device__ __align__(256) float g_Z  [(size_t)NB*CO*HH*M1*2]; // 67 MB  [b][o][h][l]{re,im}
__device__ __align__(256) float2 g_Wt[(size_t)M0*M1*CI*CO];   // 33.5MB [kl][i*64+o]{re,im}
__device__ __align__(256) float g_gamma[NB*CO];
__device__ __align__(256) float g_beta [NB*CO];

// ---- packed fp32x2 helpers (SASS FFMA2 path; PTX-only, ptxas won't emit) ----
__device__ __forceinline__ u64 pack2(float lo, float hi) {
    u64 r; asm("mov.b64 %0, {%1, %2};" : "=l"(r) : "f"(lo), "f"(hi)); return r;
}
__device__ __forceinline__ u64 dup2(float v) { return pack2(v, v); }
__device__ __forceinline__ void fma2(u64 &d, u64 a, u64 b) {
    asm("fma.rn.f32x2 %0, %1, %2, %0;" : "+l"(d) : "l"(a), "l"(b));
}
__device__ __forceinline__ u64 add2(u64 a, u64 b) {
    u64 r; asm("add.rn.f32x2 %0, %1, %2;" : "=l"(r) : "l"(a), "l"(b)); return r;
}
__device__ __forceinline__ float2 unpk2(u64 v) {
    float2 f; asm("mov.b64 {%0, %1}, %2;" : "=f"(f.x), "=f"(f.y) : "l"(v)); return f;
}

__device__ __forceinline__ float gelu_tanh(float x) {
    float u = 0.7978845608028654f * (x + 0.044715f * x * x * x);
    float t;
    asm("tanh.approx.f32 %0, %1;" : "=f"(t) : "f"(u));
    return 0.5f * x * (1.0f + t);
}

// ---------------------------------------------------------------------------
// Stage A (merged with setup): grid 4097.
//  * blocks <4096: (b,h) DFT-w via real symmetry; tables inline (exact int
//    phase); also each block transposes one 32x32 W tile into g_Wt (writes
//    only read by later mixK launch -> no intra-kernel ordering needed).
//  * block 4096: FiLM MLP only.
// ---------------------------------------------------------------------------
#define A3_U   0
#define A3_V   8448      // 64*132
#define A3_TC  16896
#define A3_TS  21282     // 16896 + 129*34
#define A3_SMEM (21282 + 128*34)   // 25634 floats

__global__ __launch_bounds__(256) void stageA5(const float* __restrict__ x,
                                               const float* __restrict__ wr,
                                               const float* __restrict__ wi,
                                               const float* __restrict__ t_emb,
                                               const float* __restrict__ w1,
                                               const float* __restrict__ b1,
                                               const float* __restrict__ w2,
                                               const float* __restrict__ b2) {
    extern __shared__ float sm[];
    int tid = threadIdx.x;
    int bid = blockIdx.x;
    const float TWO_PI = 6.283185307179586f;

    if (bid >= 4096) {                    // ---- FiLM block ----
        float* tsh = sm;
        float* hsh = sm + 1024;
        for (int p = tid; p < NB*CI; p += 256) tsh[p] = t_emb[p];
        __syncthreads();
        for (int p = tid; p < NB*CI; p += 256) {
            int b = p >> 6, j = p & 63;
            float s = b1[j];
            for (int i = 0; i < CI; i++) s += tsh[(b<<6)+i] * w1[i*CI + j];
            hsh[p] = s / (1.0f + expf(-s));
        }
        __syncthreads();
        for (int p = tid; p < NB*2*CO; p += 256) {
            int b = p >> 7, j = p & 127;
            float s = b2[j];
            for (int i = 0; i < CI; i++) s += hsh[(b<<6)+i] * w2[i*(2*CO) + j];
            if (j < CO) g_gamma[(b<<6)+j] = s;
            else        g_beta [(b<<6)+j-CO] = s;
        }
        return;
    }

    // ---- W-transpose side-task (scattered stores, hidden under A compute) ----
    {
        int p0  = (bid >> 5) << 5;
        int kl0 = (bid & 31) << 5;
        for (int q = tid; q < 1024; q += 256) {
            int r = q >> 5, c = q & 31;
            float a  = wr[(size_t)(p0 + r) * 1024 + kl0 + c];
            float bv = wi[(size_t)(p0 + r) * 1024 + kl0 + c];
            g_Wt[(size_t)(kl0 + c) * 4096 + p0 + r] = make_float2(a, bv);
        }
    }

    // ---- Stage A proper ----
    float* U  = sm + A3_U;
    float* V  = sm + A3_V;
    float* Tc = sm + A3_TC;
    float* Ts = sm + A3_TS;
    int lane = tid & 31, wid = tid >> 5;
    int b = bid >> 8;
    int h = bid & 255;

    for (int p = tid; p < 129*32; p += 256) {     // tables inline, exact phase
        int w = p >> 5, l = p & 31;
        int m = (w * l) & 255;
        float s, c; sincosf(TWO_PI * (float)m * (1.0f/256.0f), &s, &c);
        Tc[w*34 + l] = c;
        if (w < 128) Ts[w*34 + l] = -s;
    }

    size_t xbase = (size_t)b * CI * HH * WW + (size_t)h * WW;
    for (int i = wid; i < 64; i += 8) {
        const float4* xr = (const float4*)(x + xbase + (size_t)i * HH * WW);
        float4 A4 = xr[lane];
        float4 B4 = xr[63 - lane];
        float m0 = __shfl_up_sync(0xffffffffu, B4.x, 1);
        float4 u, v;
        if (lane == 0) { u.x = A4.x;      v.x = 0.0f; }
        else           { u.x = A4.x + m0; v.x = A4.x - m0; }
        u.y = A4.y + B4.w;  v.y = A4.y - B4.w;
        u.z = A4.z + B4.z;  v.z = A4.z - B4.z;
        u.w = A4.w + B4.y;  v.w = A4.w - B4.y;
        *(float4*)&U[i*132 + 4*lane] = u;
        *(float4*)&V[i*132 + 4*lane] = v;
        if (lane == 31) U[i*132 + 128] = B4.x;
    }
    __syncthreads();

    int i0 = (tid >> 4) << 2;
    int l0 = (tid & 15) << 1;
    float re[4][2], im[4][2];
#pragma unroll
    for (int r = 0; r < 4; r++) { re[r][0]=re[r][1]=im[r][0]=im[r][1]=0.0f; }

    const float* U0  = U + i0*132;
    const float* V0  = V + i0*132;
    const float* Tcp = Tc + l0;
    const float* Tsp = Ts + l0;
#pragma unroll 3
    for (int w = 0; w < 129; w++) {
        float2 c = *(float2*)&Tcp[w*34];
        float u0 = U0[w], u1 = U0[132+w], u2 = U0[264+w], u3 = U0[396+w];
        re[0][0] += u0*c.x; re[0][1] += u0*c.y;
        re[1][0] += u1*c.x; re[1][1] += u1*c.y;
        re[2][0] += u2*c.x; re[2][1] += u2*c.y;
        re[3][0] += u3*c.x; re[3][1] += u3*c.y;
    }
#pragma unroll 4
    for (int w = 0; w < 128; w++) {
        float2 s = *(float2*)&Tsp[w*34];
        float v0 = V0[w], v1 = V0[132+w], v2 = V0[264+w], v3 = V0[396+w];
        im[0][0] += v0*s.x; im[0][1] += v0*s.y;
        im[1][0] += v1*s.x; im[1][1] += v1*s.y;
        im[2][0] += v2*s.x; im[2][1] += v2*s.y;
        im[3][0] += v3*s.x; im[3][1] += v3*s.y;
    }
#pragma unroll
    for (int r = 0; r < 4; r++) {
        size_t idx = (((size_t)(b*64 + i0 + r) * 256 + h) * 64) + 2*l0;
        *(float4*)&g_Xw[idx] = make_float4(re[r][0], im[r][0], re[r][1], im[r][1]);
    }
}

// ---------------------------------------------------------------------------
// Stage B (f32x2): Xm[b,i,k,l] = sum_h Xw[b,i,h,l] * e^{-i th k h}
// ---------------------------------------------------------------------------
__global__ __launch_bounds__(256) void stageB() {
    __shared__ ulonglong2 twp[256];   // 4 KB
    int tid = threadIdx.x;
    { float s, c; sincosf(6.283185307179586f * (float)tid * (1.0f/256.0f), &s, &c);
      twp[tid] = make_ulonglong2(pack2(c, -s), pack2(s, c)); }
    __syncthreads();
    int blk = blockIdx.x;                             // b*64+i
    const float2* Xp = (const float2*)(g_Xw) + (size_t)blk * HH * M1;
    int l  = tid & 31;
    int k0 = tid >> 5;
    u64 acc2[4];
    int mt[4];
#pragma unroll
    for (int t = 0; t < 4; t++) { acc2[t] = 0ULL; mt[t] = 0; }
    for (int h = 0; h < HH; h++) {
        float2 xv = Xp[h*M1 + l];
        u64 xr2 = dup2(xv.x), xi2 = dup2(xv.y);
#pragma unroll
        for (int t = 0; t < 4; t++) {
            ulonglong2 e = twp[mt[t]];                // broadcast LDS.128
            fma2(acc2[t], e.x, xr2);
            fma2(acc2[t], e.y, xi2);
            mt[t] = (mt[t] + k0 + (t << 3)) & 255;
        }
    }
    float2* Om = (float2*)g_Xm + (size_t)blk * (M0*M1);
#pragma unroll
    for (int t = 0; t < 4; t++) {
        int k = k0 + (t << 3);
        Om[k*M1 + l] = unpk2(acc2[t]);
    }
}

// ---------------------------------------------------------------------------
// Mode mix + gamma fold. W read coalesced from pre-transposed g_Wt[kl][p].
// ---------------------------------------------------------------------------
__global__ __launch_bounds__(256) void mixK() {
    __shared__ float2 Wsh[CI*CO];    // 32 KB
    __shared__ float2 Xsh[NB*CI];    //  8 KB
    int kl = blockIdx.x;
    int tid = threadIdx.x;
    const float4* wsrc = (const float4*)(g_Wt + (size_t)kl * 4096);
    for (int q = tid; q < 2048; q += 256)
        ((float4*)Wsh)[q] = wsrc[q];                  // coalesced 16B
    for (int p = tid; p < NB*CI; p += 256)
        Xsh[p] = ((const float2*)g_Xm)[(size_t)p*1024 + kl];
    __syncthreads();
#pragma unroll
    for (int q = 0; q < 4; q++) {
        int idx = tid + q*256;                        // b*64+o
        int b = idx >> 6, o = idx & 63;
        float yr = 0.f, yi = 0.f;
#pragma unroll 8
        for (int i = 0; i < CI; i++) {
            float2 xv = Xsh[(b << 6) + i];
            float2 wv = Wsh[(i << 6) + o];
            yr += xv.x*wv.x - xv.y*wv.y;
            yi += xv.x*wv.y + xv.y*wv.x;
        }
        float g = 1.0f + g_gamma[idx];
        ((float2*)g_Yb)[(size_t)idx*1024 + kl] = make_float2(g*yr, g*yi);
    }
}

// ---------------------------------------------------------------------------
// Stage C (f32x2): Z[b,o,h,l] = sum_k Y[b,o,k,l] * e^{+i th k h}
// ---------------------------------------------------------------------------
__global__ __launch_bounds__(256) void stageC() {
    __shared__ ulonglong2 twp[256];   // 4 KB
    int tid = threadIdx.x;
    { float s, c; sincosf(6.283185307179586f * (float)tid * (1.0f/256.0f), &s, &c);
      twp[tid] = make_ulonglong2(pack2(c, s), pack2(-s, c)); }
    __syncthreads();
    int blk = blockIdx.x;                             // b*64+o
    const float2* Yp = (const float2*)g_Yb + (size_t)blk * (M0*M1);
    int l  = tid & 31;
    int h0 = tid >> 5;
    u64 acc2[32];
#pragma unroll
    for (int t = 0; t < 32; t++) acc2[t] = 0ULL;
    for (int k = 0; k < M0; k++) {
        float2 yv = Yp[k*M1 + l];
        u64 yr2 = dup2(yv.x), yi2 = dup2(yv.y);
        int mm = (k * h0) & 255;
        int st = (k << 3) & 255;
#pragma unroll
        for (int t = 0; t < 32; t++) {
            ulonglong2 e = twp[mm];                   // warp-uniform broadcast
            fma2(acc2[t], e.x, yr2);                  // (.x+=c*yr, .y+=s*yr)
            fma2(acc2[t], e.y, yi2);                  // (.x+=-s*yi,.y+=c*yi)
            mm = (mm + st) & 255;
        }
    }
    float2* Zp = (float2*)g_Z + (size_t)blk * HH * M1;
#pragma unroll
    for (int t = 0; t < 32; t++)
        Zp[(h0 + (t << 3))*M1 + l] = unpk2(acc2[t]);
}

// ---------------------------------------------------------------------------
// Fused inverse-w DFT + beta + bypass + GELU. 128 threads; thread owns TWO
// columns w=tid and w=tid+128 via parity: T[w+128,l] = (-1)^l T[w,l], so both
// share every smem operand -> FFMA2-per-LDS doubles; kernel becomes FFMA-bound.
// acc 64 regs, ~100 total; (128,4) caps 128 -> no spill, 4 CTAs/SM.
// ---------------------------------------------------------------------------
__global__ __launch_bounds__(128, 4) void specfinal5K(const float* __restrict__ x,
                                                      const float* __restrict__ bw,
                                                      const float* __restrict__ bb,
                                                      float* __restrict__ out) {
    __shared__ __align__(16) float zzRe[32*32];   // [l][o2] 4KB
    __shared__ __align__(16) float zzIm[32*32];   // [l][o2] 4KB
    __shared__ __align__(16) float bwt [64*32];   // [i][o2] 8KB
    __shared__ __align__(16) float beta_s[32];
    int tid = threadIdx.x;                        // 0..127 = w_lo
    int b     = blockIdx.x >> 9;
    int h     = (blockIdx.x >> 1) & 255;
    int obase = (blockIdx.x & 1) << 5;            // 0 or 32

    for (int p = tid; p < 2048; p += 128) {
        int i = p >> 5, o2 = p & 31;
        bwt[p] = bw[(size_t)(obase + o2) * 64 + i];
    }
    const float nrm = 1.0f / 65536.0f;
    for (int p = tid; p < 1024; p += 128) {
        int o2 = p >> 5, l = p & 31;
        float2 v = ((const float2*)g_Z)[((size_t)(b*64 + obase + o2) * 256 + h) * 32 + l];
        zzRe[l*32 + o2] = v.x * (l ? 2.0f*nrm : nrm);
        zzIm[l*32 + o2] = v.y * (-2.0f*nrm);
    }
    if (tid < 32) beta_s[tid] = g_beta[b*64 + obase + tid] + bb[obase + tid];
    __syncthreads();

    u64 alo[16], ahi[16];
#pragma unroll
    for (int p = 0; p < 16; p++) { alo[p] = 0ULL; ahi[p] = 0ULL; }

    // Bypass prefetch (completes under spectral FFMA)
    size_t xb = (size_t)b * CI * HH * WW + (size_t)h * WW + tid;
    float clo[4], chi[4];
#pragma unroll
    for (int j = 0; j < 4; j++) {
        clo[j] = x[xb       + (size_t)j * HH * WW];
        chi[j] = x[xb + 128 + (size_t)j * HH * WW];
    }

    // Spectral, rotation recurrence for w=tid; w+128 via (-1)^l (static sign).
    float cr, sr;
    sincosf(6.283185307179586f * (float)tid * (1.0f/256.0f), &sr, &cr);
    float c = 1.0f, s = 0.0f;
#pragma unroll
    for (int l = 0; l < 32; l++) {
        const float sg = (l & 1) ? -1.0f : 1.0f;
        u64 cd  = dup2(c),      sd  = dup2(s);
        u64 cdh = dup2(sg * c), sdh = dup2(sg * s);
        const ulonglong2* zr = (const ulonglong2*)(zzRe + l*32);
        const ulonglong2* zi = (const ulonglong2*)(zzIm + l*32);
#pragma unroll
        for (int og = 0; og < 8; og++) {
            ulonglong2 zp = zr[og];               // LDS.128 broadcast
            ulonglong2 ip = zi[og];
            fma2(alo[2*og    ], zp.x, cd);  fma2(alo[2*og + 1], zp.y, cd);
            fma2(alo[2*og    ], ip.x, sd);  fma2(alo[2*og + 1], ip.y, sd);
            fma2(ahi[2*og    ], zp.x, cdh); fma2(ahi[2*og + 1], zp.y, cdh);
            fma2(ahi[2*og    ], ip.x, sdh); fma2(ahi[2*og + 1], ip.y, sdh);
        }
        float cn = c*cr - s*sr;
        float sn = s*cr + c*sr;
        c = cn; s = sn;
    }

    // Bypass: both w columns share each bw row.
    for (int i = 0; i < CI; i += 4) {
        float nlo[4], nhi[4];
        if (i + 4 < CI) {
#pragma unroll
            for (int j = 0; j < 4; j++) {
                nlo[j] = x[xb       + (size_t)(i + 4 + j) * HH * WW];
                nhi[j] = x[xb + 128 + (size_t)(i + 4 + j) * HH * WW];
            }
        }
#pragma unroll
        for (int j = 0; j < 4; j++) {
            u64 xl = dup2(clo[j]), xh = dup2(chi[j]);
            const ulonglong2* wr2 = (const ulonglong2*)(bwt + ((i + j) << 5));
#pragma unroll
            for (int og = 0; og < 8; og++) {
                ulonglong2 wp = wr2[og];          // LDS.128 broadcast
                fma2(alo[2*og    ], wp.x, xl); fma2(alo[2*og + 1], wp.y, xl);
                fma2(ahi[2*og    ], wp.x, xh); fma2(ahi[2*og + 1], wp.y, xh);
            }
        }
#pragma unroll
        for (int j = 0; j < 4; j++) { clo[j] = nlo[j]; chi[j] = nhi[j]; }
    }

    size_t ob = (size_t)b * CO * HH * WW + (size_t)obase * HH * WW
              + (size_t)h * WW + tid;
#pragma unroll 4
    for (int p = 0; p < 16; p++) {
        u64 bp = *(const u64*)&beta_s[p << 1];
        float2 vlo = unpk2(add2(alo[p], bp));
        float2 vhi = unpk2(add2(ahi[p], bp));
        out[ob       + (size_t)(2*p    ) * HH * WW] = gelu_tanh(vlo.x);
        out[ob       + (size_t)(2*p + 1) * HH * WW] = gelu_tanh(vlo.y);
        out[ob + 128 + (size_t)(2*p    ) * HH * WW] = gelu_tanh(vhi.x);
        out[ob + 128 + (size_t)(2*p + 1) * HH * WW] = gelu_tanh(vhi.y);
    }
}

// ---------------------------------------------------------------------------
extern "C" void kernel_launch(void* const* d_in, const int* in_sizes, int n_in,
                              void* d_out, int out_size) {
    const float* x      = (const float*)d_in[0];
    const float* t_emb  = (const float*)d_in[1];
    const float* w_real = (const float*)d_in[2];
    const float* w_imag = (const float*)d_in[3];
    const float* fw1    = (const float*)d_in[4];
    const float* fb1    = (const float*)d_in[5];
    const float* fw2    = (const float*)d_in[6];
    const float* fb2    = (const float*)d_in[7];
    const float* bw     = (const float*)d_in[8];
    const float* bb     = (const float*)d_in[9];
    float* out = (float*)d_out;

    const int smemA = A3_SMEM * sizeof(float);                        // 102536
    cudaFuncSetAttribute(stageA5, cudaFuncAttributeMaxDynamicSharedMemorySize, smemA);

    stageA5<<<4097, 256, smemA>>>(x, w_real, w_imag, t_emb,
                                  fw1, fb1, fw2, fb2);                // 1
    stageB<<<NB*CI, 256>>>();                                         // 2
    mixK<<<M0*M1, 256>>>();                                           // 3
    stageC<<<NB*CO, 256>>>();                                         // 4 <- profiled
    specfinal5K<<<NB*HH*2, 128>>>(x, bw, bb, out);                    // 5
}

// round 14
// speedup vs baseline: 2.7116x; 1.0887x over previous
#include <cuda_runtime.h>
#include <math.h>

// Shapes (fixed for this problem)
#define NB 16
#define CI 64
#define CO 64
#define HH 256
#define WW 256
#define M0 32
#define M1 32

typedef unsigned long long u64;

// Scratch (device globals; no allocation allowed in kernel_launch)
__device__ __align__(256) float g_Xw [(size_t)NB*CI*HH*M1*2]; // 67 MB  [b][i][h][l]{re,im}
__device__ __align__(256) float g_Xm [(size_t)NB*CI*M0*M1*2]; // 8.4 MB [b][i][k*32+l]{re,im}
__device__ __align__(256) float g_Yb [(size_t)NB*CO*M0*M1*2]; // 8.4 MB [b][o][k*32+l]{re,im}
__device__ __align__(256) float g_Z  [(size_t)NB*CO*HH*M1*2]; // 67 MB  [b][o][h][l]{re,im}
__device__ __align__(256) float2 g_Wt[(size_t)M0*M1*CI*CO];   // 33.5MB [kl][i*64+o]{re,im}
__device__ __align__(256) float g_gamma[NB*CO];
__device__ __align__(256) float g_beta [NB*CO];

// ---- packed fp32x2 helpers (SASS FFMA2 path; PTX-only, ptxas won't emit) ----
__device__ __forceinline__ u64 pack2(float lo, float hi) {
    u64 r; asm("mov.b64 %0, {%1, %2};" : "=l"(r) : "f"(lo), "f"(hi)); return r;
}
__device__ __forceinline__ u64 dup2(float v) { return pack2(v, v); }
__device__ __forceinline__ void fma2(u64 &d, u64 a, u64 b) {
    asm("fma.rn.f32x2 %0, %1, %2, %0;" : "+l"(d) : "l"(a), "l"(b));
}
__device__ __forceinline__ u64 add2(u64 a, u64 b) {
    u64 r; asm("add.rn.f32x2 %0, %1, %2;" : "=l"(r) : "l"(a), "l"(b)); return r;
}
__device__ __forceinline__ float2 unpk2(u64 v) {
    float2 f; asm("mov.b64 {%0, %1}, %2;" : "=f"(f.x), "=f"(f.y) : "l"(v)); return f;
}

__device__ __forceinline__ float gelu_tanh(float x) {
    float u = 0.7978845608028654f * (x + 0.044715f * x * x * x);
    float t;
    asm("tanh.approx.f32 %0, %1;" : "=f"(t) : "f"(u));
    return 0.5f * x * (1.0f + t);
}

// ---------------------------------------------------------------------------
// Stage A (merged with setup): grid 4097. f32x2 accumulation over l-pairs.
// ---------------------------------------------------------------------------
#define A3_U   0
#define A3_V   8448      // 64*132
#define A3_TC  16896
#define A3_TS  21282     // 16896 + 129*34
#define A3_SMEM (21282 + 128*34)   // 25634 floats

__global__ __launch_bounds__(256) void stageA5(const float* __restrict__ x,
                                               const float* __restrict__ wr,
                                               const float* __restrict__ wi,
                                               const float* __restrict__ t_emb,
                                               const float* __restrict__ w1,
                                               const float* __restrict__ b1,
                                               const float* __restrict__ w2,
                                               const float* __restrict__ b2) {
    extern __shared__ float sm[];
    int tid = threadIdx.x;
    int bid = blockIdx.x;
    const float TWO_PI = 6.283185307179586f;

    if (bid >= 4096) {                    // ---- FiLM block ----
        float* tsh = sm;
        float* hsh = sm + 1024;
        for (int p = tid; p < NB*CI; p += 256) tsh[p] = t_emb[p];
        __syncthreads();
        for (int p = tid; p < NB*CI; p += 256) {
            int b = p >> 6, j = p & 63;
            float s = b1[j];
            for (int i = 0; i < CI; i++) s += tsh[(b<<6)+i] * w1[i*CI + j];
            hsh[p] = s / (1.0f + expf(-s));
        }
        __syncthreads();
        for (int p = tid; p < NB*2*CO; p += 256) {
            int b = p >> 7, j = p & 127;
            float s = b2[j];
            for (int i = 0; i < CI; i++) s += hsh[(b<<6)+i] * w2[i*(2*CO) + j];
            if (j < CO) g_gamma[(b<<6)+j] = s;
            else        g_beta [(b<<6)+j-CO] = s;
        }
        return;
    }

    // ---- W-transpose side-task ----
    {
        int p0  = (bid >> 5) << 5;
        int kl0 = (bid & 31) << 5;
        for (int q = tid; q < 1024; q += 256) {
            int r = q >> 5, c = q & 31;
            float a  = wr[(size_t)(p0 + r) * 1024 + kl0 + c];
            float bv = wi[(size_t)(p0 + r) * 1024 + kl0 + c];
            g_Wt[(size_t)(kl0 + c) * 4096 + p0 + r] = make_float2(a, bv);
        }
    }

    // ---- Stage A proper ----
    float* U  = sm + A3_U;
    float* V  = sm + A3_V;
    float* Tc = sm + A3_TC;
    float* Ts = sm + A3_TS;
    int lane = tid & 31, wid = tid >> 5;
    int b = bid >> 8;
    int h = bid & 255;

    for (int p = tid; p < 129*32; p += 256) {     // tables inline, exact phase
        int w = p >> 5, l = p & 31;
        int m = (w * l) & 255;
        float s, c; sincosf(TWO_PI * (float)m * (1.0f/256.0f), &s, &c);
        Tc[w*34 + l] = c;
        if (w < 128) Ts[w*34 + l] = -s;
    }

    size_t xbase = (size_t)b * CI * HH * WW + (size_t)h * WW;
    for (int i = wid; i < 64; i += 8) {
        const float4* xr = (const float4*)(x + xbase + (size_t)i * HH * WW);
        float4 A4 = xr[lane];
        float4 B4 = xr[63 - lane];
        float m0 = __shfl_up_sync(0xffffffffu, B4.x, 1);
        float4 u, v;
        if (lane == 0) { u.x = A4.x;      v.x = 0.0f; }
        else           { u.x = A4.x + m0; v.x = A4.x - m0; }
        u.y = A4.y + B4.w;  v.y = A4.y - B4.w;
        u.z = A4.z + B4.z;  v.z = A4.z - B4.z;
        u.w = A4.w + B4.y;  v.w = A4.w - B4.y;
        *(float4*)&U[i*132 + 4*lane] = u;
        *(float4*)&V[i*132 + 4*lane] = v;
        if (lane == 31) U[i*132 + 128] = B4.x;
    }
    __syncthreads();

    int i0 = (tid >> 4) << 2;
    int l0 = (tid & 15) << 1;
    u64 re2[4], im2[4];
#pragma unroll
    for (int r = 0; r < 4; r++) { re2[r] = 0ULL; im2[r] = 0ULL; }

    const float* U0  = U + i0*132;
    const float* V0  = V + i0*132;
    const float* Tcp = Tc + l0;
    const float* Tsp = Ts + l0;
#pragma unroll 3
    for (int w = 0; w < 129; w++) {
        u64 cd = *(const u64*)&Tcp[w*34];            // packed (cos_l0, cos_l0+1)
        fma2(re2[0], cd, dup2(U0[w]));
        fma2(re2[1], cd, dup2(U0[132+w]));
        fma2(re2[2], cd, dup2(U0[264+w]));
        fma2(re2[3], cd, dup2(U0[396+w]));
    }
#pragma unroll 4
    for (int w = 0; w < 128; w++) {
        u64 sd = *(const u64*)&Tsp[w*34];            // packed (-sin_l0, -sin_l0+1)
        fma2(im2[0], sd, dup2(V0[w]));
        fma2(im2[1], sd, dup2(V0[132+w]));
        fma2(im2[2], sd, dup2(V0[264+w]));
        fma2(im2[3], sd, dup2(V0[396+w]));
    }
#pragma unroll
    for (int r = 0; r < 4; r++) {
        float2 rr = unpk2(re2[r]);
        float2 mm = unpk2(im2[r]);
        size_t idx = (((size_t)(b*64 + i0 + r) * 256 + h) * 64) + 2*l0;
        *(float4*)&g_Xw[idx] = make_float4(rr.x, mm.x, rr.y, mm.y);
    }
}

// ---------------------------------------------------------------------------
// Stage B (f32x2 + h-parity fold): halve MACs via
//   Xm[k,l] = sum_{h<128} (x[h] + (-1)^k x[h+128]) e^{-i th k h}
// Thread owns l, k0 (k = k0+8t, all same parity -> warp-uniform sign).
// ---------------------------------------------------------------------------
__global__ __launch_bounds__(256) void stageB() {
    __shared__ ulonglong2 twp[256];   // 4 KB
    int tid = threadIdx.x;
    { float s, c; sincosf(6.283185307179586f * (float)tid * (1.0f/256.0f), &s, &c);
      twp[tid] = make_ulonglong2(pack2(c, -s), pack2(s, c)); }
    __syncthreads();
    int blk = blockIdx.x;                             // b*64+i
    const float2* Xp = (const float2*)(g_Xw) + (size_t)blk * HH * M1;
    int l  = tid & 31;
    int k0 = tid >> 5;
    float sg = (k0 & 1) ? -1.0f : 1.0f;               // (-1)^k, warp-uniform
    u64 acc2[4];
    int mt[4];
#pragma unroll
    for (int t = 0; t < 4; t++) { acc2[t] = 0ULL; mt[t] = 0; }
    for (int h = 0; h < 128; h++) {
        float2 xa = Xp[h*M1 + l];
        float2 xb = Xp[(h+128)*M1 + l];
        u64 zr2 = dup2(fmaf(sg, xb.x, xa.x));
        u64 zi2 = dup2(fmaf(sg, xb.y, xa.y));
#pragma unroll
        for (int t = 0; t < 4; t++) {
            ulonglong2 e = twp[mt[t]];                // broadcast LDS.128
            fma2(acc2[t], e.x, zr2);
            fma2(acc2[t], e.y, zi2);
            mt[t] = (mt[t] + k0 + (t << 3)) & 255;
        }
    }
    float2* Om = (float2*)g_Xm + (size_t)blk * (M0*M1);
#pragma unroll
    for (int t = 0; t < 4; t++) {
        int k = k0 + (t << 3);
        Om[k*M1 + l] = unpk2(acc2[t]);
    }
}

// ---------------------------------------------------------------------------
// Mode mix + gamma fold. W read coalesced from pre-transposed g_Wt[kl][p].
// ---------------------------------------------------------------------------
__global__ __launch_bounds__(256) void mixK() {
    __shared__ float2 Wsh[CI*CO];    // 32 KB
    __shared__ float2 Xsh[NB*CI];    //  8 KB
    int kl = blockIdx.x;
    int tid = threadIdx.x;
    const float4* wsrc = (const float4*)(g_Wt + (size_t)kl * 4096);
    for (int q = tid; q < 2048; q += 256)
        ((float4*)Wsh)[q] = wsrc[q];                  // coalesced 16B
    for (int p = tid; p < NB*CI; p += 256)
        Xsh[p] = ((const float2*)g_Xm)[(size_t)p*1024 + kl];
    __syncthreads();
#pragma unroll
    for (int q = 0; q < 4; q++) {
        int idx = tid + q*256;                        // b*64+o
        int b = idx >> 6, o = idx & 63;
        float yr = 0.f, yi = 0.f;
#pragma unroll 8
        for (int i = 0; i < CI; i++) {
            float2 xv = Xsh[(b << 6) + i];
            float2 wv = Wsh[(i << 6) + o];
            yr += xv.x*wv.x - xv.y*wv.y;
            yi += xv.x*wv.y + xv.y*wv.x;
        }
        float g = 1.0f + g_gamma[idx];
        ((float2*)g_Yb)[(size_t)idx*1024 + kl] = make_float2(g*yr, g*yi);
    }
}

// ---------------------------------------------------------------------------
// Stage C (f32x2, occupancy-fixed): grid NB*CO*4; block owns 64-h strip.
// Thread: l = tid&31, h = hq*64 + (tid>>5) + 8t, t<8 -> acc2[8] (16 regs).
// Y staged in smem once per block.
// ---------------------------------------------------------------------------
__global__ __launch_bounds__(256) void stageC() {
    __shared__ ulonglong2 twp[256];   // 4 KB
    __shared__ float2 Ysh[M0*M1];     // 8 KB
    int tid = threadIdx.x;
    { float s, c; sincosf(6.283185307179586f * (float)tid * (1.0f/256.0f), &s, &c);
      twp[tid] = make_ulonglong2(pack2(c, s), pack2(-s, c)); }
    int blk = blockIdx.x >> 2;                        // b*64+o
    int hq  = blockIdx.x & 3;
    const float2* Yp = (const float2*)g_Yb + (size_t)blk * (M0*M1);
    for (int p = tid; p < M0*M1; p += 256) Ysh[p] = Yp[p];
    __syncthreads();

    int l  = tid & 31;
    int h0 = (hq << 6) + (tid >> 5);                  // base h for this thread
    u64 acc2[8];
#pragma unroll
    for (int t = 0; t < 8; t++) acc2[t] = 0ULL;
    for (int k = 0; k < M0; k++) {
        float2 yv = Ysh[k*M1 + l];
        u64 yr2 = dup2(yv.x), yi2 = dup2(yv.y);
        int mm = (k * h0) & 255;
        int st = (k << 3) & 255;
#pragma unroll
        for (int t = 0; t < 8; t++) {
            ulonglong2 e = twp[mm];                   // warp-uniform broadcast
            fma2(acc2[t], e.x, yr2);                  // (.x+=c*yr, .y+=s*yr)
            fma2(acc2[t], e.y, yi2);                  // (.x+=-s*yi,.y+=c*yi)
            mm = (mm + st) & 255;
        }
    }
    float2* Zp = (float2*)g_Z + (size_t)blk * HH * M1;
#pragma unroll
    for (int t = 0; t < 8; t++)
        Zp[(h0 + (t << 3))*M1 + l] = unpk2(acc2[t]);
}

// ---------------------------------------------------------------------------
// Fused inverse-w DFT + beta + bypass + GELU. 128 threads; thread owns TWO
// columns w=tid, w+128 via parity; FFMA2-bound. (128,4): no spill, 4 CTAs/SM.
// ---------------------------------------------------------------------------
__global__ __launch_bounds__(128, 4) void specfinal5K(const float* __restrict__ x,
                                                      const float* __restrict__ bw,
                                                      const float* __restrict__ bb,
                                                      float* __restrict__ out) {
    __shared__ __align__(16) float zzRe[32*32];   // [l][o2] 4KB
    __shared__ __align__(16) float zzIm[32*32];   // [l][o2] 4KB
    __shared__ __align__(16) float bwt [64*32];   // [i][o2] 8KB
    __shared__ __align__(16) float beta_s[32];
    int tid = threadIdx.x;                        // 0..127 = w_lo
    int b     = blockIdx.x >> 9;
    int h     = (blockIdx.x >> 1) & 255;
    int obase = (blockIdx.x & 1) << 5;            // 0 or 32

    for (int p = tid; p < 2048; p += 128) {
        int i = p >> 5, o2 = p & 31;
        bwt[p] = bw[(size_t)(obase + o2) * 64 + i];
    }
    const float nrm = 1.0f / 65536.0f;
    for (int p = tid; p < 1024; p += 128) {
        int o2 = p >> 5, l = p & 31;
        float2 v = ((const float2*)g_Z)[((size_t)(b*64 + obase + o2) * 256 + h) * 32 + l];
        zzRe[l*32 + o2] = v.x * (l ? 2.0f*nrm : nrm);
        zzIm[l*32 + o2] = v.y * (-2.0f*nrm);
    }
    if (tid < 32) beta_s[tid] = g_beta[b*64 + obase + tid] + bb[obase + tid];
    __syncthreads();

    u64 alo[16], ahi[16];
#pragma unroll
    for (int p = 0; p < 16; p++) { alo[p] = 0ULL; ahi[p] = 0ULL; }

    // Bypass prefetch (completes under spectral FFMA)
    size_t xb = (size_t)b * CI * HH * WW + (size_t)h * WW + tid;
    float clo[4], chi[4];
#pragma unroll
    for (int j = 0; j < 4; j++) {
        clo[j] = x[xb       + (size_t)j * HH * WW];
        chi[j] = x[xb + 128 + (size_t)j * HH * WW];
    }

    // Spectral, rotation recurrence for w=tid; w+128 via (-1)^l (static sign).
    float cr, sr;
    sincosf(6.283185307179586f * (float)tid * (1.0f/256.0f), &sr, &cr);
    float c = 1.0f, s = 0.0f;
#pragma unroll
    for (int l = 0; l < 32; l++) {
        const float sg = (l & 1) ? -1.0f : 1.0f;
        u64 cd  = dup2(c),      sd  = dup2(s);
        u64 cdh = dup2(sg * c), sdh = dup2(sg * s);
        const ulonglong2* zr = (const ulonglong2*)(zzRe + l*32);
        const ulonglong2* zi = (const ulonglong2*)(zzIm + l*32);
#pragma unroll
        for (int og = 0; og < 8; og++) {
            ulonglong2 zp = zr[og];               // LDS.128 broadcast
            ulonglong2 ip = zi[og];
            fma2(alo[2*og    ], zp.x, cd);  fma2(alo[2*og + 1], zp.y, cd);
            fma2(alo[2*og    ], ip.x, sd);  fma2(alo[2*og + 1], ip.y, sd);
            fma2(ahi[2*og    ], zp.x, cdh); fma2(ahi[2*og + 1], zp.y, cdh);
            fma2(ahi[2*og    ], ip.x, sdh); fma2(ahi[2*og + 1], ip.y, sdh);
        }
        float cn = c*cr - s*sr;
        float sn = s*cr + c*sr;
        c = cn; s = sn;
    }

    // Bypass: both w columns share each bw row.
    for (int i = 0; i < CI; i += 4) {
        float nlo[4], nhi[4];
        if (i + 4 < CI) {
#pragma unroll
            for (int j = 0; j < 4; j++) {
                nlo[j] = x[xb       + (size_t)(i + 4 + j) * HH * WW];
                nhi[j] = x[xb + 128 + (size_t)(i + 4 + j) * HH * WW];
            }
        }
#pragma unroll
        for (int j = 0; j < 4; j++) {
            u64 xl = dup2(clo[j]), xh = dup2(chi[j]);
            const ulonglong2* wr2 = (const ulonglong2*)(bwt + ((i + j) << 5));
#pragma unroll
            for (int og = 0; og < 8; og++) {
                ulonglong2 wp = wr2[og];          // LDS.128 broadcast
                fma2(alo[2*og    ], wp.x, xl); fma2(alo[2*og + 1], wp.y, xl);
                fma2(ahi[2*og    ], wp.x, xh); fma2(ahi[2*og + 1], wp.y, xh);
            }
        }
#pragma unroll
        for (int j = 0; j < 4; j++) { clo[j] = nlo[j]; chi[j] = nhi[j]; }
    }

    size_t ob = (size_t)b * CO * HH * WW + (size_t)obase * HH * WW
              + (size_t)h * WW + tid;
#pragma unroll 4
    for (int p = 0; p < 16; p++) {
        u64 bp = *(const u64*)&beta_s[p << 1];
        float2 vlo = unpk2(add2(alo[p], bp));
        float2 vhi = unpk2(add2(ahi[p], bp));
        out[ob       + (size_t)(2*p    ) * HH * WW] = gelu_tanh(vlo.x);
        out[ob       + (size_t)(2*p + 1) * HH * WW] = gelu_tanh(vlo.y);
        out[ob + 128 + (size_t)(2*p    ) * HH * WW] = gelu_tanh(vhi.x);
        out[ob + 128 + (size_t)(2*p + 1) * HH * WW] = gelu_tanh(vhi.y);
    }
}

// ---------------------------------------------------------------------------
extern "C" void kernel_launch(void* const* d_in, const int* in_sizes, int n_in,
                              void* d_out, int out_size) {
    const float* x      = (const float*)d_in[0];
    const float* t_emb  = (const float*)d_in[1];
    const float* w_real = (const float*)d_in[2];
    const float* w_imag = (const float*)d_in[3];
    const float* fw1    = (const float*)d_in[4];
    const float* fb1    = (const float*)d_in[5];
    const float* fw2    = (const float*)d_in[6];
    const float* fb2    = (const float*)d_in[7];
    const float* bw     = (const float*)d_in[8];
    const float* bb     = (const float*)d_in[9];
    float* out = (float*)d_out;

    const int smemA = A3_SMEM * sizeof(float);                        // 102536
    cudaFuncSetAttribute(stageA5, cudaFuncAttributeMaxDynamicSharedMemorySize, smemA);

    stageA5<<<4097, 256, smemA>>>(x, w_real, w_imag, t_emb,
                                  fw1, fb1, fw2, fb2);                // 1
    stageB<<<NB*CI, 256>>>();                                         // 2
    mixK<<<M0*M1, 256>>>();                                           // 3
    stageC<<<NB*CO*4, 256>>>();                                       // 4 <- profiled
    specfinal5K<<<NB*HH*2, 128>>>(x, bw, bb, out);                    // 5
}